// round 12
// baseline (speedup 1.0000x reference)
#include <cuda_runtime.h>
#include <cuda_fp16.h>
#include <cstdint>

#define N_NODES   50000
#define IN_FEAT   64
#define HIDDEN    128
#define N_EDGES   800000
#define NUM_LAYERS 3
#define NBLK      ((N_NODES + 255) / 256)   // 196
#define HPAIRS    (HIDDEN / 2)              // 64 pairs per row

// ---------------- scratch (device globals; no allocation allowed) ------------
__device__ __align__(128) uint2   g_hpkA[N_NODES * HPAIRS];  // packed h (hi,lo fp16x2)
__device__ __align__(128) uint2   g_hpkB[N_NODES * HPAIRS];
__device__ __align__(128) __half2 g_t16 [N_NODES * HPAIRS];  // t in fp16 pairs
__device__ __align__(128) float   g_z   [N_NODES * HIDDEN];
__device__ int g_cnt   [N_NODES];
__device__ int g_offs  [N_NODES + 1];
__device__ int g_cursor[N_NODES];
__device__ int g_esrc  [N_EDGES];
__device__ int g_is64;
// single-pass scan state (reset by detect_k each call)
__device__ int g_aggr  [NBLK];
__device__ int g_flagA [NBLK];
__device__ int g_prefix[NBLK];
__device__ int g_flagP;
// fp16 fragment-major weights: uint2 {b0,b1}
// W_in: 2048 at 0; Wn[l]: 2048 + l*4096; Ws[l]: 2048 + (3+l)*4096
__device__ __align__(256) uint2 g_w2[2048 + 6 * 4096];

// ---------------- fp16 split helpers -----------------------------------------
__device__ __forceinline__ uint32_t pack_h2(float x, float y) {
    __half2 h = __floats2half2_rn(x, y);
    return *(uint32_t*)&h;
}
// split float2 -> fp16 hi + fp16 residual lo (A = hi + lo to ~22 bits)
__device__ __forceinline__ void split2h(float2 v, uint32_t& hi, uint32_t& lo) {
    __half2 h = __floats2half2_rn(v.x, v.y);
    float2 hf = __half22float2(h);
    __half2 l = __floats2half2_rn(v.x - hf.x, v.y - hf.y);
    hi = *(uint32_t*)&h;
    lo = *(uint32_t*)&l;
}
__device__ __forceinline__ void mma_f16(float* c, const uint32_t* a, uint32_t b0, uint32_t b1) {
    asm volatile(
        "mma.sync.aligned.m16n8k16.row.col.f32.f16.f16.f32 "
        "{%0,%1,%2,%3}, {%4,%5,%6,%7}, {%8,%9}, {%0,%1,%2,%3};"
        : "+f"(c[0]), "+f"(c[1]), "+f"(c[2]), "+f"(c[3])
        : "r"(a[0]), "r"(a[1]), "r"(a[2]), "r"(a[3]), "r"(b0), "r"(b1));
}

// ---------------- index helpers ----------------------------------------------
__device__ __forceinline__ int load_src(const int* ei, int e, int is64) {
    return is64 ? ei[2 * e] : ei[e];
}
__device__ __forceinline__ int load_dst(const int* ei, int e, int is64) {
    return is64 ? ei[2 * (N_EDGES + e)] : ei[N_EDGES + e];
}

// ---------------- dtype detect + per-call state reset ---------------------------
__global__ void detect_k(const int* __restrict__ ei) {
    int lane = threadIdx.x;
    for (int i = lane; i < NBLK; i += 32) g_flagA[i] = 0;
    if (lane == 0) g_flagP = 0;
    int bad = 0;
    for (int i = lane; i < 256; i += 32) bad |= (ei[2 * i + 1] != 0);
    bad = __any_sync(0xFFFFFFFFu, bad);
    if (lane == 0) g_is64 = !bad;
    __threadfence();
}

// ---------------- count: 4 edges per thread (MLP=4, RED no-return) ---------------
__global__ void count_k(const int* __restrict__ ei) {
    int base = (blockIdx.x * blockDim.x + threadIdx.x) * 4;
    int is64 = g_is64;
#pragma unroll
    for (int u = 0; u < 4; u++) {
        int e = base + u;
        if (e < N_EDGES) atomicAdd(&g_cnt[load_dst(ei, e, is64)], 1);
    }
}

// ---------------- single-pass scan (all 196 blocks resident; spin-sync) -----------
__global__ __launch_bounds__(256)
void scan_fused_k() {
    __shared__ int sh[256];
    __shared__ int sa[256];
    const int t   = threadIdx.x;
    const int bid = blockIdx.x;
    const int idx = bid * 256 + t;

    int v = (idx < N_NODES) ? g_cnt[idx] : 0;
    sh[t] = v;
    __syncthreads();
    for (int d = 1; d < 256; d <<= 1) {
        int n = (t >= d) ? sh[t - d] : 0;
        __syncthreads();
        sh[t] += n;
        __syncthreads();
    }
    if (t == 0) {
        g_aggr[bid] = sh[255];
        __threadfence();
        *(volatile int*)&g_flagA[bid] = 1;
    }
    if (bid == 0) {
        for (int i = t; i < NBLK; i += 256)
            while (*(volatile int*)&g_flagA[i] == 0) __nanosleep(50);
        __syncthreads();
        int a = 0;
        if (t < NBLK) a = g_aggr[t];
        sa[t] = a;
        __syncthreads();
        for (int d = 1; d < 256; d <<= 1) {
            int n = (t >= d) ? sa[t - d] : 0;
            __syncthreads();
            sa[t] += n;
            __syncthreads();
        }
        if (t < NBLK) g_prefix[t] = sa[t] - a;   // exclusive
        __threadfence();
        __syncthreads();
        if (t == 0) *(volatile int*)&g_flagP = 1;
    }
    if (t == 0)
        while (*(volatile int*)&g_flagP == 0) __nanosleep(50);
    __syncthreads();
    __threadfence();

    int ex = g_prefix[bid] + sh[t] - v;
    if (idx < N_NODES) {
        g_offs[idx]   = ex;
        g_cursor[idx] = ex;
        if (idx == N_NODES - 1) g_offs[N_NODES] = ex + v;
    }
}

// ---------------- CSR fill: 4 edges per thread (MLP=4) ----------------------------
__global__ void fill_k(const int* __restrict__ ei) {
    int base = (blockIdx.x * blockDim.x + threadIdx.x) * 4;
    int is64 = g_is64;
    int s[4], pos[4];
    bool ok[4];
#pragma unroll
    for (int u = 0; u < 4; u++) {
        int e = base + u;
        ok[u] = (e < N_EDGES);
        if (ok[u]) {
            s[u] = load_src(ei, e, is64);
            int d = load_dst(ei, e, is64);
            pos[u] = atomicAdd(&g_cursor[d], 1);
        }
    }
#pragma unroll
    for (int u = 0; u < 4; u++)
        if (ok[u]) g_esrc[pos[u]] = s[u];
}

// ---------------- weight convert: ALL weights in one kernel ------------------------
__global__ void conv_all_k(const float* __restrict__ W_in,
                           const float* __restrict__ W_nbr,
                           const float* __restrict__ W_self) {
    constexpr int TOTAL = 2048 + 6 * 4096;
    for (int idx = blockIdx.x * blockDim.x + threadIdx.x; idx < TOTAL;
         idx += gridDim.x * blockDim.x) {
        const float* W;
        int NSTEP, local;
        if (idx < 2048) {
            W = W_in; NSTEP = 4; local = idx;
        } else {
            int slot = (idx - 2048) / 4096;
            local = (idx - 2048) % 4096;
            NSTEP = 8;
            W = (slot < 3) ? (W_nbr  + (size_t)slot * HIDDEN * HIDDEN)
                           : (W_self + (size_t)(slot - 3) * HIDDEN * HIDDEN);
        }
        int lane = local & 31;
        int s = (local >> 5) % NSTEP;
        int J = local / (NSTEP * 32);
        int t = lane & 3, g = lane >> 2;
        int k0 = s * 16 + t * 2;
        int k1 = k0 + 8;
        int n = J * 8 + g;
        uint32_t b0 = pack_h2(W[(size_t)k0 * HIDDEN + n], W[(size_t)(k0 + 1) * HIDDEN + n]);
        uint32_t b1 = pack_h2(W[(size_t)k1 * HIDDEN + n], W[(size_t)(k1 + 1) * HIDDEN + n]);
        g_w2[idx] = make_uint2(b0, b1);
    }
}

// ---------------- input projection GEMM (fp32 A -> packed h out) -------------------
__global__ __launch_bounds__(256, 2)
void gemm_in_k(const float* __restrict__ A,
               const uint2* __restrict__ B2,
               const float* __restrict__ bias,
               uint2* __restrict__ Cpk, int M) {
    constexpr int K_ = IN_FEAT, NSTEP = K_ / 16;
    const int tid  = threadIdx.x;
    const int warp = tid >> 5;
    const int lane = tid & 31;
    const int g = lane >> 2, t = lane & 3;
    const int warp_m = (warp & 3) * 32;
    const int warp_n = (warp >> 2) * 64;
    const int row_base = blockIdx.x * 128 + warp_m;

    float acc[2][8][4];
#pragma unroll
    for (int mt = 0; mt < 2; mt++)
#pragma unroll
        for (int j = 0; j < 8; j++)
#pragma unroll
            for (int q = 0; q < 4; q++) acc[mt][j][q] = 0.f;

#pragma unroll
    for (int s = 0; s < NSTEP; s++) {
        uint32_t ahi[2][4], alo[2][4];
        const int c0 = s * 16 + t * 2;
#pragma unroll
        for (int mt = 0; mt < 2; mt++) {
            int r0 = row_base + mt * 16 + g;
            int r1 = r0 + 8;
            float2 v00 = make_float2(0.f, 0.f), v10 = v00, v01 = v00, v11 = v00;
            if (r0 < M) {
                v00 = *(const float2*)(A + (size_t)r0 * K_ + c0);
                v01 = *(const float2*)(A + (size_t)r0 * K_ + c0 + 8);
            }
            if (r1 < M) {
                v10 = *(const float2*)(A + (size_t)r1 * K_ + c0);
                v11 = *(const float2*)(A + (size_t)r1 * K_ + c0 + 8);
            }
            split2h(v00, ahi[mt][0], alo[mt][0]);
            split2h(v10, ahi[mt][1], alo[mt][1]);
            split2h(v01, ahi[mt][2], alo[mt][2]);
            split2h(v11, ahi[mt][3], alo[mt][3]);
        }
#pragma unroll
        for (int j = 0; j < 8; j++) {
            int J = (warp >> 2) * 8 + j;
            uint2 b = B2[(size_t)(J * NSTEP + s) * 32 + lane];
#pragma unroll
            for (int mt = 0; mt < 2; mt++) {
                mma_f16(acc[mt][j], ahi[mt], b.x, b.y);
                mma_f16(acc[mt][j], alo[mt], b.x, b.y);
            }
        }
    }
#pragma unroll
    for (int j = 0; j < 8; j++) {
        int n0 = warp_n + j * 8 + t * 2;
        float2 bv = *(const float2*)(bias + n0);
#pragma unroll
        for (int mt = 0; mt < 2; mt++) {
            int r0 = row_base + mt * 16 + g;
            int r1 = r0 + 8;
            uint32_t h0, l0, h1, l1;
            split2h(make_float2(acc[mt][j][0] + bv.x, acc[mt][j][1] + bv.y), h0, l0);
            split2h(make_float2(acc[mt][j][2] + bv.x, acc[mt][j][3] + bv.y), h1, l1);
            if (r0 < M) Cpk[(size_t)r0 * HPAIRS + (n0 >> 1)] = make_uint2(h0, l0);
            if (r1 < M) Cpk[(size_t)r1 * HPAIRS + (n0 >> 1)] = make_uint2(h1, l1);
        }
    }
}

// ---------------- dual layer GEMM: one launch, grid (391, 2) -----------------------
// blockIdx.y == 0: Tout = A @ Wn   (fp16 out)
// blockIdx.y == 1: Zout = A @ Ws + bias (fp32 out)
__global__ __launch_bounds__(256, 2)
void gemm_layer_k(const uint2* __restrict__ Apk,
                  const uint2* __restrict__ Bn,
                  const uint2* __restrict__ Bs,
                  const float* __restrict__ bias,
                  __half2* __restrict__ Tout,
                  float* __restrict__ Zout, int M) {
    constexpr int NSTEP = HIDDEN / 16;  // 8
    const int tid  = threadIdx.x;
    const int warp = tid >> 5;
    const int lane = tid & 31;
    const int g = lane >> 2, t = lane & 3;
    const int warp_m = (warp & 3) * 32;
    const int warp_n = (warp >> 2) * 64;
    const int row_base = blockIdx.x * 128 + warp_m;
    const bool is_z = (blockIdx.y != 0);
    const uint2* __restrict__ B2 = is_z ? Bs : Bn;

    float acc[2][8][4];
#pragma unroll
    for (int mt = 0; mt < 2; mt++)
#pragma unroll
        for (int j = 0; j < 8; j++)
#pragma unroll
            for (int q = 0; q < 4; q++) acc[mt][j][q] = 0.f;

#pragma unroll
    for (int s = 0; s < NSTEP; s++) {
        uint32_t ahi[2][4], alo[2][4];
        const int pr = s * 8 + t;
#pragma unroll
        for (int mt = 0; mt < 2; mt++) {
            int r0 = row_base + mt * 16 + g;
            int r1 = r0 + 8;
            uint2 zz = make_uint2(0u, 0u);
            uint2 p00 = zz, p01 = zz, p10 = zz, p11 = zz;
            if (r0 < M) {
                p00 = Apk[(size_t)r0 * HPAIRS + pr];
                p01 = Apk[(size_t)r0 * HPAIRS + pr + 4];
            }
            if (r1 < M) {
                p10 = Apk[(size_t)r1 * HPAIRS + pr];
                p11 = Apk[(size_t)r1 * HPAIRS + pr + 4];
            }
            ahi[mt][0] = p00.x; alo[mt][0] = p00.y;
            ahi[mt][1] = p10.x; alo[mt][1] = p10.y;
            ahi[mt][2] = p01.x; alo[mt][2] = p01.y;
            ahi[mt][3] = p11.x; alo[mt][3] = p11.y;
        }
#pragma unroll
        for (int j = 0; j < 8; j++) {
            int J = (warp >> 2) * 8 + j;
            uint2 b = B2[(size_t)(J * NSTEP + s) * 32 + lane];
#pragma unroll
            for (int mt = 0; mt < 2; mt++) {
                mma_f16(acc[mt][j], ahi[mt], b.x, b.y);
                mma_f16(acc[mt][j], alo[mt], b.x, b.y);
            }
        }
    }

    if (is_z) {
#pragma unroll
        for (int j = 0; j < 8; j++) {
            int n0 = warp_n + j * 8 + t * 2;
            float2 bv = *(const float2*)(bias + n0);
#pragma unroll
            for (int mt = 0; mt < 2; mt++) {
                int r0 = row_base + mt * 16 + g;
                int r1 = r0 + 8;
                if (r0 < M)
                    *(float2*)(Zout + (size_t)r0 * HIDDEN + n0) =
                        make_float2(acc[mt][j][0] + bv.x, acc[mt][j][1] + bv.y);
                if (r1 < M)
                    *(float2*)(Zout + (size_t)r1 * HIDDEN + n0) =
                        make_float2(acc[mt][j][2] + bv.x, acc[mt][j][3] + bv.y);
            }
        }
    } else {
#pragma unroll
        for (int j = 0; j < 8; j++) {
            int n0 = warp_n + j * 8 + t * 2;
#pragma unroll
            for (int mt = 0; mt < 2; mt++) {
                int r0 = row_base + mt * 16 + g;
                int r1 = r0 + 8;
                if (r0 < M)
                    Tout[(size_t)r0 * HPAIRS + (n0 >> 1)] =
                        __floats2half2_rn(acc[mt][j][0], acc[mt][j][1]);
                if (r1 < M)
                    Tout[(size_t)r1 * HPAIRS + (n0 >> 1)] =
                        __floats2half2_rn(acc[mt][j][2], acc[mt][j][3]);
            }
        }
    }
}

// ---------------- fused gather: 2 nodes/warp, 16 lanes x 16B per row ----------------
// r = elu( z[n] + (sum t[src])/max(deg,1) );  LAST: write fp32 out, else packed h
template <int LAST>
__global__ __launch_bounds__(256)
void gather_fused_k(const __half2* __restrict__ t16,
                    const float* __restrict__ z,
                    void* __restrict__ outv) {
    int gtid = blockIdx.x * blockDim.x + threadIdx.x;
    int w    = gtid >> 5;                  // warp id
    int lane = gtid & 31;
    int sub  = lane >> 4;                  // 0/1 half-warp
    int sl   = lane & 15;                  // lane within half
    int node = w * 2 + sub;
    if (node >= N_NODES) return;
    int p = sl * 4;                        // pair base: 4 half2 pairs = 16B

    int start = g_offs[node];
    int end   = g_offs[node + 1];

    float acc[8];
#pragma unroll
    for (int i = 0; i < 8; i++) acc[i] = 0.f;

    int e = start;
    for (; e + 4 <= end; e += 4) {
        int si[4];
#pragma unroll
        for (int u = 0; u < 4; u++) si[u] = g_esrc[e + u];
        uint4 q[4];
#pragma unroll
        for (int u = 0; u < 4; u++)
            q[u] = __ldg((const uint4*)(t16 + (size_t)si[u] * HPAIRS + p));
#pragma unroll
        for (int u = 0; u < 4; u++) {
            float2 a0 = __half22float2(*(__half2*)&q[u].x);
            float2 a1 = __half22float2(*(__half2*)&q[u].y);
            float2 a2 = __half22float2(*(__half2*)&q[u].z);
            float2 a3 = __half22float2(*(__half2*)&q[u].w);
            acc[0] += a0.x; acc[1] += a0.y;
            acc[2] += a1.x; acc[3] += a1.y;
            acc[4] += a2.x; acc[5] += a2.y;
            acc[6] += a3.x; acc[7] += a3.y;
        }
    }
    for (; e < end; e++) {
        int s = g_esrc[e];
        uint4 q = __ldg((const uint4*)(t16 + (size_t)s * HPAIRS + p));
        float2 a0 = __half22float2(*(__half2*)&q.x);
        float2 a1 = __half22float2(*(__half2*)&q.y);
        float2 a2 = __half22float2(*(__half2*)&q.z);
        float2 a3 = __half22float2(*(__half2*)&q.w);
        acc[0] += a0.x; acc[1] += a0.y;
        acc[2] += a1.x; acc[3] += a1.y;
        acc[4] += a2.x; acc[5] += a2.y;
        acc[6] += a3.x; acc[7] += a3.y;
    }

    float inv = 1.0f / fmaxf((float)(end - start), 1.0f);
    int c = sl * 8;                        // fp32 column base (8 cols per lane)
    float4 z0 = __ldg((const float4*)(z + (size_t)node * HIDDEN + c));
    float4 z1 = __ldg((const float4*)(z + (size_t)node * HIDDEN + c + 4));
    float r[8];
    r[0] = z0.x + acc[0] * inv; r[1] = z0.y + acc[1] * inv;
    r[2] = z0.z + acc[2] * inv; r[3] = z0.w + acc[3] * inv;
    r[4] = z1.x + acc[4] * inv; r[5] = z1.y + acc[5] * inv;
    r[6] = z1.z + acc[6] * inv; r[7] = z1.w + acc[7] * inv;
#pragma unroll
    for (int i = 0; i < 8; i++) r[i] = (r[i] > 0.f) ? r[i] : expm1f(r[i]);

    if (LAST) {
        float* o = (float*)outv + (size_t)node * HIDDEN + c;
        *(float4*)(o)     = make_float4(r[0], r[1], r[2], r[3]);
        *(float4*)(o + 4) = make_float4(r[4], r[5], r[6], r[7]);
    } else {
        uint2* Cpk = (uint2*)outv + (size_t)node * HPAIRS + p;
#pragma unroll
        for (int i = 0; i < 4; i++) {
            uint32_t hh, ll;
            split2h(make_float2(r[2 * i], r[2 * i + 1]), hh, ll);
            Cpk[i] = make_uint2(hh, ll);
        }
    }
}

// ---------------- launch ----------------------------------------------------------
extern "C" void kernel_launch(void* const* d_in, const int* in_sizes, int n_in,
                              void* d_out, int out_size) {
    const float* x      = (const float*)d_in[0];
    const int*   ei     = (const int*)d_in[1];
    const float* W_in   = (const float*)d_in[2];
    const float* b_in   = (const float*)d_in[3];
    const float* W_self = (const float*)d_in[4];
    const float* b_self = (const float*)d_in[5];
    const float* W_nbr  = (const float*)d_in[6];
    float*       out    = (float*)d_out;

    uint2*   hpkA; cudaGetSymbolAddress((void**)&hpkA, g_hpkA);
    uint2*   hpkB; cudaGetSymbolAddress((void**)&hpkB, g_hpkB);
    __half2* t16;  cudaGetSymbolAddress((void**)&t16,  g_t16);
    float*   z;    cudaGetSymbolAddress((void**)&z,    g_z);
    int*     cnt;  cudaGetSymbolAddress((void**)&cnt,  g_cnt);
    uint2*   w2;   cudaGetSymbolAddress((void**)&w2,   g_w2);

    const int M = N_NODES;
    const int gemm_blocks = (M + 127) / 128;            // 391
    const int edge4_blocks = (N_EDGES / 4 + 255) / 256; // 782
    const int gather_blocks = (N_NODES / 2 * 32 + 255) / 256;  // 3125

    // ---- CSR build ----
    detect_k<<<1, 32>>>(ei);
    cudaMemsetAsync(cnt, 0, N_NODES * sizeof(int));
    count_k<<<edge4_blocks, 256>>>(ei);
    scan_fused_k<<<NBLK, 256>>>();
    fill_k<<<edge4_blocks, 256>>>(ei);

    // ---- all weight packing in one launch ----
    conv_all_k<<<64, 256>>>(W_in, W_nbr, W_self);

    // ---- input projection: hpkA = pack(x @ W_in + b_in) ----
    gemm_in_k<<<gemm_blocks, 256>>>(x, w2, b_in, hpkA, M);

    const uint2* hcur = hpkA;
    for (int l = 0; l < NUM_LAYERS; l++) {
        const float* bs = b_self + (size_t)l * HIDDEN;
        const uint2* wn = w2 + 2048 + l * 4096;
        const uint2* ws = w2 + 2048 + (3 + l) * 4096;
        uint2* hnext = (hcur == hpkA) ? hpkB : hpkA;

        dim3 grid(gemm_blocks, 2);
        gemm_layer_k<<<grid, 256>>>(hcur, wn, ws, bs, t16, z, M);
        if (l == NUM_LAYERS - 1)
            gather_fused_k<1><<<gather_blocks, 256>>>(t16, z, out);
        else
            gather_fused_k<0><<<gather_blocks, 256>>>(t16, z, hnext);

        hcur = hnext;
    }
}

// round 13
// speedup vs baseline: 1.0265x; 1.0265x over previous
#include <cuda_runtime.h>
#include <cuda_fp16.h>
#include <cstdint>

#define N_NODES   50000
#define IN_FEAT   64
#define HIDDEN    128
#define N_EDGES   800000
#define NUM_LAYERS 3
#define NBLK      ((N_NODES + 255) / 256)   // 196
#define HPAIRS    (HIDDEN / 2)              // 64 pairs per row

// ---------------- scratch (device globals; no allocation allowed) ------------
__device__ __align__(128) uint2   g_hpkA[N_NODES * HPAIRS];  // packed h (hi,lo fp16x2)
__device__ __align__(128) uint2   g_hpkB[N_NODES * HPAIRS];
__device__ __align__(128) __half2 g_t16 [N_NODES * HPAIRS];  // t in fp16 pairs
__device__ __align__(128) float   g_z   [N_NODES * HIDDEN];
__device__ int g_cnt  [N_NODES];
__device__ int g_offs [N_NODES + 1];
__device__ int g_rank [N_EDGES];
__device__ int g_esrc [N_EDGES];
__device__ int g_is64;
// single-pass scan state (reset by init_k each call)
__device__ int g_aggr  [NBLK];
__device__ int g_flagA [NBLK];
__device__ int g_prefix[NBLK];
__device__ int g_flagP;
// fp16 fragment-major weights: uint2 {b0,b1}
// W_in: 2048 at 0; Wn[l]: 2048 + l*4096; Ws[l]: 2048 + (3+l)*4096
__device__ __align__(256) uint2 g_w2[2048 + 6 * 4096];

// ---------------- fp16 split helpers -----------------------------------------
__device__ __forceinline__ uint32_t pack_h2(float x, float y) {
    __half2 h = __floats2half2_rn(x, y);
    return *(uint32_t*)&h;
}
// split float2 -> fp16 hi + fp16 residual lo (A = hi + lo to ~22 bits)
__device__ __forceinline__ void split2h(float2 v, uint32_t& hi, uint32_t& lo) {
    __half2 h = __floats2half2_rn(v.x, v.y);
    float2 hf = __half22float2(h);
    __half2 l = __floats2half2_rn(v.x - hf.x, v.y - hf.y);
    hi = *(uint32_t*)&h;
    lo = *(uint32_t*)&l;
}
__device__ __forceinline__ void mma_f16(float* c, const uint32_t* a, uint32_t b0, uint32_t b1) {
    asm volatile(
        "mma.sync.aligned.m16n8k16.row.col.f32.f16.f16.f32 "
        "{%0,%1,%2,%3}, {%4,%5,%6,%7}, {%8,%9}, {%0,%1,%2,%3};"
        : "+f"(c[0]), "+f"(c[1]), "+f"(c[2]), "+f"(c[3])
        : "r"(a[0]), "r"(a[1]), "r"(a[2]), "r"(a[3]), "r"(b0), "r"(b1));
}

// ---------------- index helpers ----------------------------------------------
__device__ __forceinline__ int load_src(const int* ei, int e, int is64) {
    return is64 ? ei[2 * e] : ei[e];
}
__device__ __forceinline__ int load_dst(const int* ei, int e, int is64) {
    return is64 ? ei[2 * (N_EDGES + e)] : ei[N_EDGES + e];
}

// ---------------- init: zero cnt + reset scan flags + dtype detect ---------------
__global__ __launch_bounds__(256)
void init_k(const int* __restrict__ ei) {
    int idx = blockIdx.x * 256 + threadIdx.x;
    if (idx < N_NODES) g_cnt[idx] = 0;
    if (blockIdx.x == 0) {
        int t = threadIdx.x;
        if (t < NBLK) g_flagA[t] = 0;
        if (t == 0) g_flagP = 0;
        if (t < 32) {
            int bad = 0;
            for (int i = t; i < 256; i += 32) bad |= (ei[2 * i + 1] != 0);
            bad = __any_sync(0xFFFFFFFFu, bad);
            if (t == 0) g_is64 = !bad;
        }
    }
}

// ---------------- count: rank[e] = ticket within dst segment ----------------------
__global__ void count_k(const int* __restrict__ ei) {
    int e = blockIdx.x * blockDim.x + threadIdx.x;
    if (e >= N_EDGES) return;
    int d = load_dst(ei, e, g_is64);
    g_rank[e] = atomicAdd(&g_cnt[d], 1);
}

// ---------------- single-pass scan (all 196 blocks resident; spin-sync) -----------
__global__ __launch_bounds__(256)
void scan_fused_k() {
    __shared__ int sh[256];
    __shared__ int sa[256];
    const int t   = threadIdx.x;
    const int bid = blockIdx.x;
    const int idx = bid * 256 + t;

    int v = (idx < N_NODES) ? g_cnt[idx] : 0;
    sh[t] = v;
    __syncthreads();
    for (int d = 1; d < 256; d <<= 1) {
        int n = (t >= d) ? sh[t - d] : 0;
        __syncthreads();
        sh[t] += n;
        __syncthreads();
    }
    if (t == 0) {
        g_aggr[bid] = sh[255];
        __threadfence();
        *(volatile int*)&g_flagA[bid] = 1;
    }
    if (bid == 0) {
        for (int i = t; i < NBLK; i += 256)
            while (*(volatile int*)&g_flagA[i] == 0) __nanosleep(50);
        __syncthreads();
        int a = 0;
        if (t < NBLK) a = g_aggr[t];
        sa[t] = a;
        __syncthreads();
        for (int d = 1; d < 256; d <<= 1) {
            int n = (t >= d) ? sa[t - d] : 0;
            __syncthreads();
            sa[t] += n;
            __syncthreads();
        }
        if (t < NBLK) g_prefix[t] = sa[t] - a;   // exclusive
        __threadfence();
        __syncthreads();
        if (t == 0) *(volatile int*)&g_flagP = 1;
    }
    if (t == 0)
        while (*(volatile int*)&g_flagP == 0) __nanosleep(50);
    __syncthreads();
    __threadfence();

    int ex = g_prefix[bid] + sh[t] - v;
    if (idx < N_NODES) {
        g_offs[idx] = ex;
        if (idx == N_NODES - 1) g_offs[N_NODES] = ex + v;
    }
}

// ---------------- CSR fill: atomic-free (pos = offs[dst] + rank[e]) ----------------
__global__ void fill_k(const int* __restrict__ ei) {
    int e = blockIdx.x * blockDim.x + threadIdx.x;
    if (e >= N_EDGES) return;
    int is64 = g_is64;
    int s = load_src(ei, e, is64);
    int d = load_dst(ei, e, is64);
    g_esrc[g_offs[d] + g_rank[e]] = s;
}

// ---------------- weight convert: ALL weights in one kernel ------------------------
__global__ void conv_all_k(const float* __restrict__ W_in,
                           const float* __restrict__ W_nbr,
                           const float* __restrict__ W_self) {
    constexpr int TOTAL = 2048 + 6 * 4096;
    for (int idx = blockIdx.x * blockDim.x + threadIdx.x; idx < TOTAL;
         idx += gridDim.x * blockDim.x) {
        const float* W;
        int NSTEP, local;
        if (idx < 2048) {
            W = W_in; NSTEP = 4; local = idx;
        } else {
            int slot = (idx - 2048) / 4096;
            local = (idx - 2048) % 4096;
            NSTEP = 8;
            W = (slot < 3) ? (W_nbr  + (size_t)slot * HIDDEN * HIDDEN)
                           : (W_self + (size_t)(slot - 3) * HIDDEN * HIDDEN);
        }
        int lane = local & 31;
        int s = (local >> 5) % NSTEP;
        int J = local / (NSTEP * 32);
        int t = lane & 3, g = lane >> 2;
        int k0 = s * 16 + t * 2;
        int k1 = k0 + 8;
        int n = J * 8 + g;
        uint32_t b0 = pack_h2(W[(size_t)k0 * HIDDEN + n], W[(size_t)(k0 + 1) * HIDDEN + n]);
        uint32_t b1 = pack_h2(W[(size_t)k1 * HIDDEN + n], W[(size_t)(k1 + 1) * HIDDEN + n]);
        g_w2[idx] = make_uint2(b0, b1);
    }
}

// ---------------- input projection GEMM (fp32 A -> packed h out) -------------------
__global__ __launch_bounds__(256, 2)
void gemm_in_k(const float* __restrict__ A,
               const uint2* __restrict__ B2,
               const float* __restrict__ bias,
               uint2* __restrict__ Cpk, int M) {
    constexpr int K_ = IN_FEAT, NSTEP = K_ / 16;
    const int tid  = threadIdx.x;
    const int warp = tid >> 5;
    const int lane = tid & 31;
    const int g = lane >> 2, t = lane & 3;
    const int warp_m = (warp & 3) * 32;
    const int warp_n = (warp >> 2) * 64;
    const int row_base = blockIdx.x * 128 + warp_m;

    float acc[2][8][4];
#pragma unroll
    for (int mt = 0; mt < 2; mt++)
#pragma unroll
        for (int j = 0; j < 8; j++)
#pragma unroll
            for (int q = 0; q < 4; q++) acc[mt][j][q] = 0.f;

#pragma unroll
    for (int s = 0; s < NSTEP; s++) {
        uint32_t ahi[2][4], alo[2][4];
        const int c0 = s * 16 + t * 2;
#pragma unroll
        for (int mt = 0; mt < 2; mt++) {
            int r0 = row_base + mt * 16 + g;
            int r1 = r0 + 8;
            float2 v00 = make_float2(0.f, 0.f), v10 = v00, v01 = v00, v11 = v00;
            if (r0 < M) {
                v00 = *(const float2*)(A + (size_t)r0 * K_ + c0);
                v01 = *(const float2*)(A + (size_t)r0 * K_ + c0 + 8);
            }
            if (r1 < M) {
                v10 = *(const float2*)(A + (size_t)r1 * K_ + c0);
                v11 = *(const float2*)(A + (size_t)r1 * K_ + c0 + 8);
            }
            split2h(v00, ahi[mt][0], alo[mt][0]);
            split2h(v10, ahi[mt][1], alo[mt][1]);
            split2h(v01, ahi[mt][2], alo[mt][2]);
            split2h(v11, ahi[mt][3], alo[mt][3]);
        }
#pragma unroll
        for (int j = 0; j < 8; j++) {
            int J = (warp >> 2) * 8 + j;
            uint2 b = B2[(size_t)(J * NSTEP + s) * 32 + lane];
#pragma unroll
            for (int mt = 0; mt < 2; mt++) {
                mma_f16(acc[mt][j], ahi[mt], b.x, b.y);
                mma_f16(acc[mt][j], alo[mt], b.x, b.y);
            }
        }
    }
#pragma unroll
    for (int j = 0; j < 8; j++) {
        int n0 = warp_n + j * 8 + t * 2;
        float2 bv = *(const float2*)(bias + n0);
#pragma unroll
        for (int mt = 0; mt < 2; mt++) {
            int r0 = row_base + mt * 16 + g;
            int r1 = r0 + 8;
            uint32_t h0, l0, h1, l1;
            split2h(make_float2(acc[mt][j][0] + bv.x, acc[mt][j][1] + bv.y), h0, l0);
            split2h(make_float2(acc[mt][j][2] + bv.x, acc[mt][j][3] + bv.y), h1, l1);
            if (r0 < M) Cpk[(size_t)r0 * HPAIRS + (n0 >> 1)] = make_uint2(h0, l0);
            if (r1 < M) Cpk[(size_t)r1 * HPAIRS + (n0 >> 1)] = make_uint2(h1, l1);
        }
    }
}

// ---------------- dual layer GEMM: one launch, grid (391, 2) -----------------------
// blockIdx.y == 0: Tout = A @ Wn   (fp16 out)
// blockIdx.y == 1: Zout = A @ Ws + bias (fp32 out)
__global__ __launch_bounds__(256, 2)
void gemm_layer_k(const uint2* __restrict__ Apk,
                  const uint2* __restrict__ Bn,
                  const uint2* __restrict__ Bs,
                  const float* __restrict__ bias,
                  __half2* __restrict__ Tout,
                  float* __restrict__ Zout, int M) {
    constexpr int NSTEP = HIDDEN / 16;  // 8
    const int tid  = threadIdx.x;
    const int warp = tid >> 5;
    const int lane = tid & 31;
    const int g = lane >> 2, t = lane & 3;
    const int warp_m = (warp & 3) * 32;
    const int warp_n = (warp >> 2) * 64;
    const int row_base = blockIdx.x * 128 + warp_m;
    const bool is_z = (blockIdx.y != 0);
    const uint2* __restrict__ B2 = is_z ? Bs : Bn;

    float acc[2][8][4];
#pragma unroll
    for (int mt = 0; mt < 2; mt++)
#pragma unroll
        for (int j = 0; j < 8; j++)
#pragma unroll
            for (int q = 0; q < 4; q++) acc[mt][j][q] = 0.f;

#pragma unroll
    for (int s = 0; s < NSTEP; s++) {
        uint32_t ahi[2][4], alo[2][4];
        const int pr = s * 8 + t;
#pragma unroll
        for (int mt = 0; mt < 2; mt++) {
            int r0 = row_base + mt * 16 + g;
            int r1 = r0 + 8;
            uint2 zz = make_uint2(0u, 0u);
            uint2 p00 = zz, p01 = zz, p10 = zz, p11 = zz;
            if (r0 < M) {
                p00 = Apk[(size_t)r0 * HPAIRS + pr];
                p01 = Apk[(size_t)r0 * HPAIRS + pr + 4];
            }
            if (r1 < M) {
                p10 = Apk[(size_t)r1 * HPAIRS + pr];
                p11 = Apk[(size_t)r1 * HPAIRS + pr + 4];
            }
            ahi[mt][0] = p00.x; alo[mt][0] = p00.y;
            ahi[mt][1] = p10.x; alo[mt][1] = p10.y;
            ahi[mt][2] = p01.x; alo[mt][2] = p01.y;
            ahi[mt][3] = p11.x; alo[mt][3] = p11.y;
        }
#pragma unroll
        for (int j = 0; j < 8; j++) {
            int J = (warp >> 2) * 8 + j;
            uint2 b = B2[(size_t)(J * NSTEP + s) * 32 + lane];
#pragma unroll
            for (int mt = 0; mt < 2; mt++) {
                mma_f16(acc[mt][j], ahi[mt], b.x, b.y);
                mma_f16(acc[mt][j], alo[mt], b.x, b.y);
            }
        }
    }

    if (is_z) {
#pragma unroll
        for (int j = 0; j < 8; j++) {
            int n0 = warp_n + j * 8 + t * 2;
            float2 bv = *(const float2*)(bias + n0);
#pragma unroll
            for (int mt = 0; mt < 2; mt++) {
                int r0 = row_base + mt * 16 + g;
                int r1 = r0 + 8;
                if (r0 < M)
                    *(float2*)(Zout + (size_t)r0 * HIDDEN + n0) =
                        make_float2(acc[mt][j][0] + bv.x, acc[mt][j][1] + bv.y);
                if (r1 < M)
                    *(float2*)(Zout + (size_t)r1 * HIDDEN + n0) =
                        make_float2(acc[mt][j][2] + bv.x, acc[mt][j][3] + bv.y);
            }
        }
    } else {
#pragma unroll
        for (int j = 0; j < 8; j++) {
            int n0 = warp_n + j * 8 + t * 2;
#pragma unroll
            for (int mt = 0; mt < 2; mt++) {
                int r0 = row_base + mt * 16 + g;
                int r1 = r0 + 8;
                if (r0 < M)
                    Tout[(size_t)r0 * HPAIRS + (n0 >> 1)] =
                        __floats2half2_rn(acc[mt][j][0], acc[mt][j][1]);
                if (r1 < M)
                    Tout[(size_t)r1 * HPAIRS + (n0 >> 1)] =
                        __floats2half2_rn(acc[mt][j][2], acc[mt][j][3]);
            }
        }
    }
}

// ---------------- fused gather + epilogue (t in fp16; R10 form) ---------------------
// r = elu( z[n] + (sum t[src])/max(deg,1) );  LAST: write fp32 out, else packed h
template <int LAST>
__global__ __launch_bounds__(256)
void gather_fused_k(const __half2* __restrict__ t16,
                    const float* __restrict__ z,
                    void* __restrict__ outv) {
    int gtid = blockIdx.x * blockDim.x + threadIdx.x;
    int node = gtid >> 5;
    if (node >= N_NODES) return;
    int lane = gtid & 31;
    int c = lane * 4;               // fp32 column base
    int p = lane * 2;               // half2 pair base

    int start = g_offs[node];
    int end   = g_offs[node + 1];

    float4 acc = make_float4(0.f, 0.f, 0.f, 0.f);
    int e = start;
    for (; e + 4 <= end; e += 4) {
        int si[4];
#pragma unroll
        for (int u = 0; u < 4; u++) si[u] = g_esrc[e + u];
        uint2 q[4];
#pragma unroll
        for (int u = 0; u < 4; u++)
            q[u] = __ldg((const uint2*)(t16 + (size_t)si[u] * HPAIRS + p));
#pragma unroll
        for (int u = 0; u < 4; u++) {
            float2 a = __half22float2(*(__half2*)&q[u].x);
            float2 b = __half22float2(*(__half2*)&q[u].y);
            acc.x += a.x; acc.y += a.y; acc.z += b.x; acc.w += b.y;
        }
    }
    for (; e < end; e++) {
        int s = g_esrc[e];
        uint2 q = __ldg((const uint2*)(t16 + (size_t)s * HPAIRS + p));
        float2 a = __half22float2(*(__half2*)&q.x), b = __half22float2(*(__half2*)&q.y);
        acc.x += a.x; acc.y += a.y; acc.z += b.x; acc.w += b.y;
    }

    float inv = 1.0f / fmaxf((float)(end - start), 1.0f);
    float4 zv = __ldg((const float4*)(z + (size_t)node * HIDDEN + c));
    float4 r;
    r.x = zv.x + acc.x * inv;
    r.y = zv.y + acc.y * inv;
    r.z = zv.z + acc.z * inv;
    r.w = zv.w + acc.w * inv;
    r.x = (r.x > 0.f) ? r.x : expm1f(r.x);
    r.y = (r.y > 0.f) ? r.y : expm1f(r.y);
    r.z = (r.z > 0.f) ? r.z : expm1f(r.z);
    r.w = (r.w > 0.f) ? r.w : expm1f(r.w);

    if (LAST) {
        *(float4*)((float*)outv + (size_t)node * HIDDEN + c) = r;
    } else {
        uint32_t h0, l0, h1, l1;
        split2h(make_float2(r.x, r.y), h0, l0);
        split2h(make_float2(r.z, r.w), h1, l1);
        *(uint4*)((uint2*)outv + (size_t)node * HPAIRS + p) =
            make_uint4(h0, l0, h1, l1);
    }
}

// ---------------- launch ----------------------------------------------------------
extern "C" void kernel_launch(void* const* d_in, const int* in_sizes, int n_in,
                              void* d_out, int out_size) {
    const float* x      = (const float*)d_in[0];
    const int*   ei     = (const int*)d_in[1];
    const float* W_in   = (const float*)d_in[2];
    const float* b_in   = (const float*)d_in[3];
    const float* W_self = (const float*)d_in[4];
    const float* b_self = (const float*)d_in[5];
    const float* W_nbr  = (const float*)d_in[6];
    float*       out    = (float*)d_out;

    uint2*   hpkA; cudaGetSymbolAddress((void**)&hpkA, g_hpkA);
    uint2*   hpkB; cudaGetSymbolAddress((void**)&hpkB, g_hpkB);
    __half2* t16;  cudaGetSymbolAddress((void**)&t16,  g_t16);
    float*   z;    cudaGetSymbolAddress((void**)&z,    g_z);
    uint2*   w2;   cudaGetSymbolAddress((void**)&w2,   g_w2);

    const int M = N_NODES;
    const int gemm_blocks = (M + 127) / 128;             // 391
    const int edge_blocks = (N_EDGES + 255) / 256;       // 3125

    // ---- CSR build (4 launches, fill atomic-free) ----
    init_k<<<NBLK, 256>>>(ei);
    count_k<<<edge_blocks, 256>>>(ei);
    scan_fused_k<<<NBLK, 256>>>();
    fill_k<<<edge_blocks, 256>>>(ei);

    // ---- all weight packing in one launch ----
    conv_all_k<<<64, 256>>>(W_in, W_nbr, W_self);

    // ---- input projection: hpkA = pack(x @ W_in + b_in) ----
    gemm_in_k<<<gemm_blocks, 256>>>(x, w2, b_in, hpkA, M);

    const uint2* hcur = hpkA;
    for (int l = 0; l < NUM_LAYERS; l++) {
        const float* bs = b_self + (size_t)l * HIDDEN;
        const uint2* wn = w2 + 2048 + l * 4096;
        const uint2* ws = w2 + 2048 + (3 + l) * 4096;
        uint2* hnext = (hcur == hpkA) ? hpkB : hpkA;

        dim3 grid(gemm_blocks, 2);
        gemm_layer_k<<<grid, 256>>>(hcur, wn, ws, bs, t16, z, M);
        if (l == NUM_LAYERS - 1)
            gather_fused_k<1><<<(N_NODES * 32 + 255) / 256, 256>>>(t16, z, out);
        else
            gather_fused_k<0><<<(N_NODES * 32 + 255) / 256, 256>>>(t16, z, hnext);

        hcur = hnext;
    }
}

// round 14
// speedup vs baseline: 1.0676x; 1.0400x over previous
#include <cuda_runtime.h>
#include <cuda_fp16.h>
#include <cstdint>

#define N_NODES   50000
#define IN_FEAT   64
#define HIDDEN    128
#define N_EDGES   800000
#define NUM_LAYERS 3
#define NBLK      ((N_NODES + 255) / 256)   // 196
#define HPAIRS    (HIDDEN / 2)              // 64 pairs per row
#define GEMM_BLOCKS ((N_NODES + 127) / 128) // 391
#define FILL_BLOCKS 391                     // 391*2048 >= 800000

// ---------------- scratch (device globals; no allocation allowed) ------------
__device__ __align__(128) uint2   g_hpkA[N_NODES * HPAIRS];  // packed h (hi,lo fp16x2)
__device__ __align__(128) uint2   g_hpkB[N_NODES * HPAIRS];
__device__ __align__(128) __half2 g_t16 [N_NODES * HPAIRS];  // t in fp16 pairs
__device__ __align__(128) float   g_z   [N_NODES * HIDDEN];
__device__ int g_cnt  [N_NODES];
__device__ int g_offs [N_NODES + 1];
__device__ int g_rank [N_EDGES];
__device__ int g_esrc [N_EDGES];
__device__ int g_is64;
// single-pass scan state (reset by initconv_k each call)
__device__ int g_aggr  [NBLK];
__device__ int g_flagA [NBLK];
__device__ int g_prefix[NBLK];
__device__ int g_flagP;
__device__ int g_done;
// fp16 fragment-major weights: uint2 {b0,b1}
// W_in: 2048 at 0; Wn[l]: 2048 + l*4096; Ws[l]: 2048 + (3+l)*4096
__device__ __align__(256) uint2 g_w2[2048 + 6 * 4096];

// ---------------- fp16 split helpers -----------------------------------------
__device__ __forceinline__ uint32_t pack_h2(float x, float y) {
    __half2 h = __floats2half2_rn(x, y);
    return *(uint32_t*)&h;
}
// split float2 -> fp16 hi + fp16 residual lo (A = hi + lo to ~22 bits)
__device__ __forceinline__ void split2h(float2 v, uint32_t& hi, uint32_t& lo) {
    __half2 h = __floats2half2_rn(v.x, v.y);
    float2 hf = __half22float2(h);
    __half2 l = __floats2half2_rn(v.x - hf.x, v.y - hf.y);
    hi = *(uint32_t*)&h;
    lo = *(uint32_t*)&l;
}
__device__ __forceinline__ void mma_f16(float* c, const uint32_t* a, uint32_t b0, uint32_t b1) {
    asm volatile(
        "mma.sync.aligned.m16n8k16.row.col.f32.f16.f16.f32 "
        "{%0,%1,%2,%3}, {%4,%5,%6,%7}, {%8,%9}, {%0,%1,%2,%3};"
        : "+f"(c[0]), "+f"(c[1]), "+f"(c[2]), "+f"(c[3])
        : "r"(a[0]), "r"(a[1]), "r"(a[2]), "r"(a[3]), "r"(b0), "r"(b1));
}

// ---------------- index helpers ----------------------------------------------
__device__ __forceinline__ int load_src(const int* ei, int e, int is64) {
    return is64 ? ei[2 * e] : ei[e];
}
__device__ __forceinline__ int load_dst(const int* ei, int e, int is64) {
    return is64 ? ei[2 * (N_EDGES + e)] : ei[N_EDGES + e];
}

// ---------------- weight-fragment conversion (one element) --------------------
__device__ __forceinline__ void conv_one(int idx,
                                         const float* __restrict__ W_in,
                                         const float* __restrict__ W_nbr,
                                         const float* __restrict__ W_self) {
    const float* W;
    int NSTEP, local;
    if (idx < 2048) {
        W = W_in; NSTEP = 4; local = idx;
    } else {
        int slot = (idx - 2048) / 4096;
        local = (idx - 2048) % 4096;
        NSTEP = 8;
        W = (slot < 3) ? (W_nbr  + (size_t)slot * HIDDEN * HIDDEN)
                       : (W_self + (size_t)(slot - 3) * HIDDEN * HIDDEN);
    }
    int lane = local & 31;
    int s = (local >> 5) % NSTEP;
    int J = local / (NSTEP * 32);
    int t = lane & 3, g = lane >> 2;
    int k0 = s * 16 + t * 2;
    int k1 = k0 + 8;
    int n = J * 8 + g;
    uint32_t b0 = pack_h2(W[(size_t)k0 * HIDDEN + n], W[(size_t)(k0 + 1) * HIDDEN + n]);
    uint32_t b1 = pack_h2(W[(size_t)k1 * HIDDEN + n], W[(size_t)(k1 + 1) * HIDDEN + n]);
    g_w2[idx] = make_uint2(b0, b1);
}

// ---------------- kernel A: init (cnt/flags/detect) + weight conversion ----------
__global__ __launch_bounds__(256)
void initconv_k(const int* __restrict__ ei,
                const float* __restrict__ W_in,
                const float* __restrict__ W_nbr,
                const float* __restrict__ W_self) {
    int idx = blockIdx.x * 256 + threadIdx.x;
    if (idx < N_NODES) g_cnt[idx] = 0;
    constexpr int TOTAL = 2048 + 6 * 4096;   // 26624 < 196*256
    if (idx < TOTAL) conv_one(idx, W_in, W_nbr, W_self);
    if (blockIdx.x == 0) {
        int t = threadIdx.x;
        if (t < NBLK) g_flagA[t] = 0;
        if (t == 0) { g_flagP = 0; g_done = 0; }
        if (t < 32) {
            int bad = 0;
            for (int i = t; i < 256; i += 32) bad |= (ei[2 * i + 1] != 0);
            bad = __any_sync(0xFFFFFFFFu, bad);
            if (t == 0) g_is64 = !bad;
        }
    }
}

// ---------------- kernel B: input-proj GEMM (blocks < 391) + edge count (rest) -----
__global__ __launch_bounds__(256, 2)
void gemm_in_count_k(const float* __restrict__ A,
                     const uint2* __restrict__ B2,
                     const float* __restrict__ bias,
                     uint2* __restrict__ Cpk,
                     const int* __restrict__ ei, int M) {
    if (blockIdx.x >= GEMM_BLOCKS) {
        // ---- count path: rank[e] = ticket within dst segment ----
        int cb = blockIdx.x - GEMM_BLOCKS;          // 0..195
        int is64 = g_is64;
        for (int e = cb * 256 + threadIdx.x; e < N_EDGES; e += NBLK * 256) {
            int d = load_dst(ei, e, is64);
            g_rank[e] = atomicAdd(&g_cnt[d], 1);
        }
        return;
    }
    // ---- GEMM path ----
    constexpr int K_ = IN_FEAT, NSTEP = K_ / 16;
    const int tid  = threadIdx.x;
    const int warp = tid >> 5;
    const int lane = tid & 31;
    const int g = lane >> 2, t = lane & 3;
    const int warp_m = (warp & 3) * 32;
    const int warp_n = (warp >> 2) * 64;
    const int row_base = blockIdx.x * 128 + warp_m;

    float acc[2][8][4];
#pragma unroll
    for (int mt = 0; mt < 2; mt++)
#pragma unroll
        for (int j = 0; j < 8; j++)
#pragma unroll
            for (int q = 0; q < 4; q++) acc[mt][j][q] = 0.f;

#pragma unroll
    for (int s = 0; s < NSTEP; s++) {
        uint32_t ahi[2][4], alo[2][4];
        const int c0 = s * 16 + t * 2;
#pragma unroll
        for (int mt = 0; mt < 2; mt++) {
            int r0 = row_base + mt * 16 + g;
            int r1 = r0 + 8;
            float2 v00 = make_float2(0.f, 0.f), v10 = v00, v01 = v00, v11 = v00;
            if (r0 < M) {
                v00 = *(const float2*)(A + (size_t)r0 * K_ + c0);
                v01 = *(const float2*)(A + (size_t)r0 * K_ + c0 + 8);
            }
            if (r1 < M) {
                v10 = *(const float2*)(A + (size_t)r1 * K_ + c0);
                v11 = *(const float2*)(A + (size_t)r1 * K_ + c0 + 8);
            }
            split2h(v00, ahi[mt][0], alo[mt][0]);
            split2h(v10, ahi[mt][1], alo[mt][1]);
            split2h(v01, ahi[mt][2], alo[mt][2]);
            split2h(v11, ahi[mt][3], alo[mt][3]);
        }
#pragma unroll
        for (int j = 0; j < 8; j++) {
            int J = (warp >> 2) * 8 + j;
            uint2 b = B2[(size_t)(J * NSTEP + s) * 32 + lane];
#pragma unroll
            for (int mt = 0; mt < 2; mt++) {
                mma_f16(acc[mt][j], ahi[mt], b.x, b.y);
                mma_f16(acc[mt][j], alo[mt], b.x, b.y);
            }
        }
    }
#pragma unroll
    for (int j = 0; j < 8; j++) {
        int n0 = warp_n + j * 8 + t * 2;
        float2 bv = *(const float2*)(bias + n0);
#pragma unroll
        for (int mt = 0; mt < 2; mt++) {
            int r0 = row_base + mt * 16 + g;
            int r1 = r0 + 8;
            uint32_t h0, l0, h1, l1;
            split2h(make_float2(acc[mt][j][0] + bv.x, acc[mt][j][1] + bv.y), h0, l0);
            split2h(make_float2(acc[mt][j][2] + bv.x, acc[mt][j][3] + bv.y), h1, l1);
            if (r0 < M) Cpk[(size_t)r0 * HPAIRS + (n0 >> 1)] = make_uint2(h0, l0);
            if (r1 < M) Cpk[(size_t)r1 * HPAIRS + (n0 >> 1)] = make_uint2(h1, l1);
        }
    }
}

// ---------------- kernel C: scan (blocks < 196) + fill (rest, waits on g_done) -----
__global__ __launch_bounds__(256)
void scanfill_k(const int* __restrict__ ei) {
    const int t = threadIdx.x;
    if (blockIdx.x < NBLK) {
        // ---- scan path (all 196 blocks resident; spin-sync) ----
        __shared__ int sh[256];
        __shared__ int sa[256];
        const int bid = blockIdx.x;
        const int idx = bid * 256 + t;

        int v = (idx < N_NODES) ? g_cnt[idx] : 0;
        sh[t] = v;
        __syncthreads();
        for (int d = 1; d < 256; d <<= 1) {
            int n = (t >= d) ? sh[t - d] : 0;
            __syncthreads();
            sh[t] += n;
            __syncthreads();
        }
        if (t == 0) {
            g_aggr[bid] = sh[255];
            __threadfence();
            *(volatile int*)&g_flagA[bid] = 1;
        }
        if (bid == 0) {
            for (int i = t; i < NBLK; i += 256)
                while (*(volatile int*)&g_flagA[i] == 0) __nanosleep(50);
            __syncthreads();
            int a = 0;
            if (t < NBLK) a = g_aggr[t];
            sa[t] = a;
            __syncthreads();
            for (int d = 1; d < 256; d <<= 1) {
                int n = (t >= d) ? sa[t - d] : 0;
                __syncthreads();
                sa[t] += n;
                __syncthreads();
            }
            if (t < NBLK) g_prefix[t] = sa[t] - a;   // exclusive
            __threadfence();
            __syncthreads();
            if (t == 0) *(volatile int*)&g_flagP = 1;
        }
        if (t == 0)
            while (*(volatile int*)&g_flagP == 0) __nanosleep(50);
        __syncthreads();
        __threadfence();

        int ex = g_prefix[bid] + sh[t] - v;
        if (idx < N_NODES) {
            g_offs[idx] = ex;
            if (idx == N_NODES - 1) g_offs[N_NODES] = ex + v;
        }
        // release: this block's offs are visible
        __threadfence();
        __syncthreads();
        if (t == 0) atomicAdd(&g_done, 1);
    } else {
        // ---- fill path: preload (independent), wait for offs, scatter ----
        int fb = blockIdx.x - NBLK;          // 0..390
        int base = fb * 2048 + t;
        int is64 = g_is64;
        int s[8], d[8], r[8];
        bool ok[8];
#pragma unroll
        for (int u = 0; u < 8; u++) {
            int e = base + u * 256;
            ok[u] = (e < N_EDGES);
            if (ok[u]) {
                s[u] = load_src(ei, e, is64);
                d[u] = load_dst(ei, e, is64);
                r[u] = g_rank[e];
            }
        }
        if (t == 0)
            while (*(volatile int*)&g_done < NBLK) __nanosleep(100);
        __syncthreads();
        __threadfence();
#pragma unroll
        for (int u = 0; u < 8; u++)
            if (ok[u]) g_esrc[g_offs[d[u]] + r[u]] = s[u];
    }
}

// ---------------- dual layer GEMM: one launch, grid (391, 2) -----------------------
// blockIdx.y == 0: Tout = A @ Wn   (fp16 out)
// blockIdx.y == 1: Zout = A @ Ws + bias (fp32 out)
__global__ __launch_bounds__(256, 2)
void gemm_layer_k(const uint2* __restrict__ Apk,
                  const uint2* __restrict__ Bn,
                  const uint2* __restrict__ Bs,
                  const float* __restrict__ bias,
                  __half2* __restrict__ Tout,
                  float* __restrict__ Zout, int M) {
    constexpr int NSTEP = HIDDEN / 16;  // 8
    const int tid  = threadIdx.x;
    const int warp = tid >> 5;
    const int lane = tid & 31;
    const int g = lane >> 2, t = lane & 3;
    const int warp_m = (warp & 3) * 32;
    const int warp_n = (warp >> 2) * 64;
    const int row_base = blockIdx.x * 128 + warp_m;
    const bool is_z = (blockIdx.y != 0);
    const uint2* __restrict__ B2 = is_z ? Bs : Bn;

    float acc[2][8][4];
#pragma unroll
    for (int mt = 0; mt < 2; mt++)
#pragma unroll
        for (int j = 0; j < 8; j++)
#pragma unroll
            for (int q = 0; q < 4; q++) acc[mt][j][q] = 0.f;

#pragma unroll
    for (int s = 0; s < NSTEP; s++) {
        uint32_t ahi[2][4], alo[2][4];
        const int pr = s * 8 + t;
#pragma unroll
        for (int mt = 0; mt < 2; mt++) {
            int r0 = row_base + mt * 16 + g;
            int r1 = r0 + 8;
            uint2 zz = make_uint2(0u, 0u);
            uint2 p00 = zz, p01 = zz, p10 = zz, p11 = zz;
            if (r0 < M) {
                p00 = Apk[(size_t)r0 * HPAIRS + pr];
                p01 = Apk[(size_t)r0 * HPAIRS + pr + 4];
            }
            if (r1 < M) {
                p10 = Apk[(size_t)r1 * HPAIRS + pr];
                p11 = Apk[(size_t)r1 * HPAIRS + pr + 4];
            }
            ahi[mt][0] = p00.x; alo[mt][0] = p00.y;
            ahi[mt][1] = p10.x; alo[mt][1] = p10.y;
            ahi[mt][2] = p01.x; alo[mt][2] = p01.y;
            ahi[mt][3] = p11.x; alo[mt][3] = p11.y;
        }
#pragma unroll
        for (int j = 0; j < 8; j++) {
            int J = (warp >> 2) * 8 + j;
            uint2 b = B2[(size_t)(J * NSTEP + s) * 32 + lane];
#pragma unroll
            for (int mt = 0; mt < 2; mt++) {
                mma_f16(acc[mt][j], ahi[mt], b.x, b.y);
                mma_f16(acc[mt][j], alo[mt], b.x, b.y);
            }
        }
    }

    if (is_z) {
#pragma unroll
        for (int j = 0; j < 8; j++) {
            int n0 = warp_n + j * 8 + t * 2;
            float2 bv = *(const float2*)(bias + n0);
#pragma unroll
            for (int mt = 0; mt < 2; mt++) {
                int r0 = row_base + mt * 16 + g;
                int r1 = r0 + 8;
                if (r0 < M)
                    *(float2*)(Zout + (size_t)r0 * HIDDEN + n0) =
                        make_float2(acc[mt][j][0] + bv.x, acc[mt][j][1] + bv.y);
                if (r1 < M)
                    *(float2*)(Zout + (size_t)r1 * HIDDEN + n0) =
                        make_float2(acc[mt][j][2] + bv.x, acc[mt][j][3] + bv.y);
            }
        }
    } else {
#pragma unroll
        for (int j = 0; j < 8; j++) {
            int n0 = warp_n + j * 8 + t * 2;
#pragma unroll
            for (int mt = 0; mt < 2; mt++) {
                int r0 = row_base + mt * 16 + g;
                int r1 = r0 + 8;
                if (r0 < M)
                    Tout[(size_t)r0 * HPAIRS + (n0 >> 1)] =
                        __floats2half2_rn(acc[mt][j][0], acc[mt][j][1]);
                if (r1 < M)
                    Tout[(size_t)r1 * HPAIRS + (n0 >> 1)] =
                        __floats2half2_rn(acc[mt][j][2], acc[mt][j][3]);
            }
        }
    }
}

// ---------------- fused gather + epilogue (t in fp16) -------------------------------
// r = elu( z[n] + (sum t[src])/max(deg,1) );  LAST: write fp32 out, else packed h
template <int LAST>
__global__ __launch_bounds__(256)
void gather_fused_k(const __half2* __restrict__ t16,
                    const float* __restrict__ z,
                    void* __restrict__ outv) {
    int gtid = blockIdx.x * blockDim.x + threadIdx.x;
    int node = gtid >> 5;
    if (node >= N_NODES) return;
    int lane = gtid & 31;
    int c = lane * 4;               // fp32 column base
    int p = lane * 2;               // half2 pair base

    int start = g_offs[node];
    int end   = g_offs[node + 1];

    float4 acc = make_float4(0.f, 0.f, 0.f, 0.f);
    int e = start;
    for (; e + 4 <= end; e += 4) {
        int si[4];
#pragma unroll
        for (int u = 0; u < 4; u++) si[u] = g_esrc[e + u];
        uint2 q[4];
#pragma unroll
        for (int u = 0; u < 4; u++)
            q[u] = __ldg((const uint2*)(t16 + (size_t)si[u] * HPAIRS + p));
#pragma unroll
        for (int u = 0; u < 4; u++) {
            float2 a = __half22float2(*(__half2*)&q[u].x);
            float2 b = __half22float2(*(__half2*)&q[u].y);
            acc.x += a.x; acc.y += a.y; acc.z += b.x; acc.w += b.y;
        }
    }
    for (; e < end; e++) {
        int s = g_esrc[e];
        uint2 q = __ldg((const uint2*)(t16 + (size_t)s * HPAIRS + p));
        float2 a = __half22float2(*(__half2*)&q.x), b = __half22float2(*(__half2*)&q.y);
        acc.x += a.x; acc.y += a.y; acc.z += b.x; acc.w += b.y;
    }

    float inv = 1.0f / fmaxf((float)(end - start), 1.0f);
    float4 zv = __ldg((const float4*)(z + (size_t)node * HIDDEN + c));
    float4 r;
    r.x = zv.x + acc.x * inv;
    r.y = zv.y + acc.y * inv;
    r.z = zv.z + acc.z * inv;
    r.w = zv.w + acc.w * inv;
    r.x = (r.x > 0.f) ? r.x : expm1f(r.x);
    r.y = (r.y > 0.f) ? r.y : expm1f(r.y);
    r.z = (r.z > 0.f) ? r.z : expm1f(r.z);
    r.w = (r.w > 0.f) ? r.w : expm1f(r.w);

    if (LAST) {
        *(float4*)((float*)outv + (size_t)node * HIDDEN + c) = r;
    } else {
        uint32_t h0, l0, h1, l1;
        split2h(make_float2(r.x, r.y), h0, l0);
        split2h(make_float2(r.z, r.w), h1, l1);
        *(uint4*)((uint2*)outv + (size_t)node * HPAIRS + p) =
            make_uint4(h0, l0, h1, l1);
    }
}

// ---------------- launch ----------------------------------------------------------
extern "C" void kernel_launch(void* const* d_in, const int* in_sizes, int n_in,
                              void* d_out, int out_size) {
    const float* x      = (const float*)d_in[0];
    const int*   ei     = (const int*)d_in[1];
    const float* W_in   = (const float*)d_in[2];
    const float* b_in   = (const float*)d_in[3];
    const float* W_self = (const float*)d_in[4];
    const float* b_self = (const float*)d_in[5];
    const float* W_nbr  = (const float*)d_in[6];
    float*       out    = (float*)d_out;

    uint2*   hpkA; cudaGetSymbolAddress((void**)&hpkA, g_hpkA);
    uint2*   hpkB; cudaGetSymbolAddress((void**)&hpkB, g_hpkB);
    __half2* t16;  cudaGetSymbolAddress((void**)&t16,  g_t16);
    float*   z;    cudaGetSymbolAddress((void**)&z,    g_z);
    uint2*   w2;   cudaGetSymbolAddress((void**)&w2,   g_w2);

    const int M = N_NODES;

    // A: init + weight conversion (independent work, one launch)
    initconv_k<<<NBLK, 256>>>(ei, W_in, W_nbr, W_self);
    // B: input projection GEMM + edge count (overlapped)
    gemm_in_count_k<<<GEMM_BLOCKS + NBLK, 256>>>(x, w2, b_in, hpkA, ei, M);
    // C: scan + fill (overlapped via g_done dependency)
    scanfill_k<<<NBLK + FILL_BLOCKS, 256>>>(ei);

    const uint2* hcur = hpkA;
    for (int l = 0; l < NUM_LAYERS; l++) {
        const float* bs = b_self + (size_t)l * HIDDEN;
        const uint2* wn = w2 + 2048 + l * 4096;
        const uint2* ws = w2 + 2048 + (3 + l) * 4096;
        uint2* hnext = (hcur == hpkA) ? hpkB : hpkA;

        dim3 grid(GEMM_BLOCKS, 2);
        gemm_layer_k<<<grid, 256>>>(hcur, wn, ws, bs, t16, z, M);
        if (l == NUM_LAYERS - 1)
            gather_fused_k<1><<<(N_NODES * 32 + 255) / 256, 256>>>(t16, z, out);
        else
            gather_fused_k<0><<<(N_NODES * 32 + 255) / 256, 256>>>(t16, z, hnext);

        hcur = hnext;
    }
}

// round 15
// speedup vs baseline: 1.1276x; 1.0562x over previous
#include <cuda_runtime.h>
#include <cuda_fp16.h>
#include <cstdint>

#define N_NODES   50000
#define IN_FEAT   64
#define HIDDEN    128
#define N_EDGES   800000
#define NUM_LAYERS 3
#define NBLK      ((N_NODES + 255) / 256)   // 196
#define HPAIRS    (HIDDEN / 2)              // 64 pairs per row
#define GEMM_BLOCKS ((N_NODES + 127) / 128) // 391
#define FILL_BLOCKS 391                     // 391*2048 >= 800000

// weight fragments, uint4 {b0(Jeven),b1(Jeven),b0(Jodd),b1(Jodd)}
// W_in: 1024 u4 at 0; Wn[l]: 1024 + l*2048; Ws[l]: 1024 + (3+l)*2048
#define W4_TOTAL (1024 + 6 * 2048)          // 13312

// ---------------- scratch (device globals; no allocation allowed) ------------
__device__ __align__(128) uint2   g_hpkA[N_NODES * HPAIRS];  // permuted packed h
__device__ __align__(128) uint2   g_hpkB[N_NODES * HPAIRS];
__device__ __align__(128) __half2 g_t16 [N_NODES * HPAIRS];  // permuted t fp16
__device__ __align__(128) float   g_z   [N_NODES * HIDDEN];  // plain fp32
__device__ int g_cnt  [N_NODES];
__device__ int g_offs [N_NODES + 1];
__device__ int g_rank [N_EDGES];
__device__ int g_esrc [N_EDGES];
__device__ int g_is64;
__device__ int g_aggr  [NBLK];
__device__ int g_flagA [NBLK];
__device__ int g_prefix[NBLK];
__device__ int g_flagP;
__device__ int g_done;
__device__ __align__(256) uint4 g_w4[W4_TOTAL];

// ---------------- helpers ------------------------------------------------------
__device__ __forceinline__ uint32_t pack_h2(float x, float y) {
    __half2 h = __floats2half2_rn(x, y);
    return *(uint32_t*)&h;
}
__device__ __forceinline__ void split2h(float2 v, uint32_t& hi, uint32_t& lo) {
    __half2 h = __floats2half2_rn(v.x, v.y);
    float2 hf = __half22float2(h);
    __half2 l = __floats2half2_rn(v.x - hf.x, v.y - hf.y);
    hi = *(uint32_t*)&h;
    lo = *(uint32_t*)&l;
}
__device__ __forceinline__ void mma_f16(float* c, const uint32_t* a, uint32_t b0, uint32_t b1) {
    asm volatile(
        "mma.sync.aligned.m16n8k16.row.col.f32.f16.f16.f32 "
        "{%0,%1,%2,%3}, {%4,%5,%6,%7}, {%8,%9}, {%0,%1,%2,%3};"
        : "+f"(c[0]), "+f"(c[1]), "+f"(c[2]), "+f"(c[3])
        : "r"(a[0]), "r"(a[1]), "r"(a[2]), "r"(a[3]), "r"(b0), "r"(b1));
}
// permuted position of logical pair q: pairs (8s+t, 8s+t+4) land adjacent
__device__ __forceinline__ int permp(int q) {
    int s = q >> 3, u = q & 7;
    return 8 * s + ((u < 4) ? (u << 1) : (((u - 4) << 1) | 1));
}
__device__ __forceinline__ int load_src(const int* ei, int e, int is64) {
    return is64 ? ei[2 * e] : ei[e];
}
__device__ __forceinline__ int load_dst(const int* ei, int e, int is64) {
    return is64 ? ei[2 * (N_EDGES + e)] : ei[N_EDGES + e];
}

// ---------------- weight-fragment conversion (one uint4) ------------------------
__device__ __forceinline__ void conv_one(int idx,
                                         const float* __restrict__ W_in,
                                         const float* __restrict__ W_nbr,
                                         const float* __restrict__ W_self) {
    const float* W;
    int NSTEP, local;
    if (idx < 1024) {
        W = W_in; NSTEP = 4; local = idx;
    } else {
        int slot = (idx - 1024) / 2048;
        local = (idx - 1024) % 2048;
        NSTEP = 8;
        W = (slot < 3) ? (W_nbr  + (size_t)slot * HIDDEN * HIDDEN)
                       : (W_self + (size_t)(slot - 3) * HIDDEN * HIDDEN);
    }
    int lane = local & 31;
    int s = (local >> 5) % NSTEP;
    int q = local / (NSTEP * 32);          // J-pair 0..7
    int t = lane & 3, g = lane >> 2;
    int k0 = s * 16 + t * 2;
    int k1 = k0 + 8;
    uint32_t v[4];
#pragma unroll
    for (int h = 0; h < 2; h++) {
        int n = (2 * q + h) * 8 + g;
        v[2 * h + 0] = pack_h2(W[(size_t)k0 * HIDDEN + n], W[(size_t)(k0 + 1) * HIDDEN + n]);
        v[2 * h + 1] = pack_h2(W[(size_t)k1 * HIDDEN + n], W[(size_t)(k1 + 1) * HIDDEN + n]);
    }
    g_w4[idx] = make_uint4(v[0], v[1], v[2], v[3]);
}

// ---------------- kernel A: init (cnt/flags/detect) + weight conversion ----------
__global__ __launch_bounds__(256)
void initconv_k(const int* __restrict__ ei,
                const float* __restrict__ W_in,
                const float* __restrict__ W_nbr,
                const float* __restrict__ W_self) {
    int idx = blockIdx.x * 256 + threadIdx.x;
    if (idx < N_NODES) g_cnt[idx] = 0;
    if (idx < W4_TOTAL) conv_one(idx, W_in, W_nbr, W_self);
    if (blockIdx.x == 0) {
        int t = threadIdx.x;
        if (t < NBLK) g_flagA[t] = 0;
        if (t == 0) { g_flagP = 0; g_done = 0; }
        if (t < 32) {
            int bad = 0;
            for (int i = t; i < 256; i += 32) bad |= (ei[2 * i + 1] != 0);
            bad = __any_sync(0xFFFFFFFFu, bad);
            if (t == 0) g_is64 = !bad;
        }
    }
}

// ---------------- kernel B: input-proj GEMM (blocks < 391) + edge count ----------
__global__ __launch_bounds__(256, 2)
void gemm_in_count_k(const float* __restrict__ A,
                     const uint4* __restrict__ B4,
                     const float* __restrict__ bias,
                     uint2* __restrict__ Cpk,
                     const int* __restrict__ ei, int M) {
    if (blockIdx.x >= GEMM_BLOCKS) {
        int cb = blockIdx.x - GEMM_BLOCKS;
        int is64 = g_is64;
        for (int e = cb * 256 + threadIdx.x; e < N_EDGES; e += NBLK * 256) {
            int d = load_dst(ei, e, is64);
            g_rank[e] = atomicAdd(&g_cnt[d], 1);
        }
        return;
    }
    constexpr int K_ = IN_FEAT, NSTEP = K_ / 16;
    const int tid  = threadIdx.x;
    const int warp = tid >> 5;
    const int lane = tid & 31;
    const int g = lane >> 2, t = lane & 3;
    const int warp_m = (warp & 3) * 32;
    const int warp_n = (warp >> 2) * 64;
    const int qbase  = (warp >> 2) * 4;       // J-pair base
    const int row_base = blockIdx.x * 128 + warp_m;

    float acc[2][8][4];
#pragma unroll
    for (int mt = 0; mt < 2; mt++)
#pragma unroll
        for (int j = 0; j < 8; j++)
#pragma unroll
            for (int q = 0; q < 4; q++) acc[mt][j][q] = 0.f;

#pragma unroll
    for (int s = 0; s < NSTEP; s++) {
        uint32_t ahi[2][4], alo[2][4];
        const int c0 = s * 16 + t * 2;
#pragma unroll
        for (int mt = 0; mt < 2; mt++) {
            int r0 = row_base + mt * 16 + g;
            int r1 = r0 + 8;
            float2 v00 = make_float2(0.f, 0.f), v10 = v00, v01 = v00, v11 = v00;
            if (r0 < M) {
                v00 = *(const float2*)(A + (size_t)r0 * K_ + c0);
                v01 = *(const float2*)(A + (size_t)r0 * K_ + c0 + 8);
            }
            if (r1 < M) {
                v10 = *(const float2*)(A + (size_t)r1 * K_ + c0);
                v11 = *(const float2*)(A + (size_t)r1 * K_ + c0 + 8);
            }
            split2h(v00, ahi[mt][0], alo[mt][0]);
            split2h(v10, ahi[mt][1], alo[mt][1]);
            split2h(v01, ahi[mt][2], alo[mt][2]);
            split2h(v11, ahi[mt][3], alo[mt][3]);
        }
#pragma unroll
        for (int jp = 0; jp < 4; jp++) {
            uint4 b = B4[(size_t)((qbase + jp) * NSTEP + s) * 32 + lane];
#pragma unroll
            for (int mt = 0; mt < 2; mt++) {
                mma_f16(acc[mt][2 * jp],     ahi[mt], b.x, b.y);
                mma_f16(acc[mt][2 * jp],     alo[mt], b.x, b.y);
                mma_f16(acc[mt][2 * jp + 1], ahi[mt], b.z, b.w);
                mma_f16(acc[mt][2 * jp + 1], alo[mt], b.z, b.w);
            }
        }
    }
#pragma unroll
    for (int j = 0; j < 8; j++) {
        int n0 = warp_n + j * 8 + t * 2;
        int pq = permp(n0 >> 1);
        float2 bv = *(const float2*)(bias + n0);
#pragma unroll
        for (int mt = 0; mt < 2; mt++) {
            int r0 = row_base + mt * 16 + g;
            int r1 = r0 + 8;
            uint32_t h0, l0, h1, l1;
            split2h(make_float2(acc[mt][j][0] + bv.x, acc[mt][j][1] + bv.y), h0, l0);
            split2h(make_float2(acc[mt][j][2] + bv.x, acc[mt][j][3] + bv.y), h1, l1);
            if (r0 < M) Cpk[(size_t)r0 * HPAIRS + pq] = make_uint2(h0, l0);
            if (r1 < M) Cpk[(size_t)r1 * HPAIRS + pq] = make_uint2(h1, l1);
        }
    }
}

// ---------------- kernel C: scan (blocks < 196) + fill (rest) ---------------------
__global__ __launch_bounds__(256)
void scanfill_k(const int* __restrict__ ei) {
    const int t = threadIdx.x;
    if (blockIdx.x < NBLK) {
        __shared__ int sh[256];
        __shared__ int sa[256];
        const int bid = blockIdx.x;
        const int idx = bid * 256 + t;

        int v = (idx < N_NODES) ? g_cnt[idx] : 0;
        sh[t] = v;
        __syncthreads();
        for (int d = 1; d < 256; d <<= 1) {
            int n = (t >= d) ? sh[t - d] : 0;
            __syncthreads();
            sh[t] += n;
            __syncthreads();
        }
        if (t == 0) {
            g_aggr[bid] = sh[255];
            __threadfence();
            *(volatile int*)&g_flagA[bid] = 1;
        }
        if (bid == 0) {
            for (int i = t; i < NBLK; i += 256)
                while (*(volatile int*)&g_flagA[i] == 0) __nanosleep(50);
            __syncthreads();
            int a = 0;
            if (t < NBLK) a = g_aggr[t];
            sa[t] = a;
            __syncthreads();
            for (int d = 1; d < 256; d <<= 1) {
                int n = (t >= d) ? sa[t - d] : 0;
                __syncthreads();
                sa[t] += n;
                __syncthreads();
            }
            if (t < NBLK) g_prefix[t] = sa[t] - a;
            __threadfence();
            __syncthreads();
            if (t == 0) *(volatile int*)&g_flagP = 1;
        }
        if (t == 0)
            while (*(volatile int*)&g_flagP == 0) __nanosleep(50);
        __syncthreads();
        __threadfence();

        int ex = g_prefix[bid] + sh[t] - v;
        if (idx < N_NODES) {
            g_offs[idx] = ex;
            if (idx == N_NODES - 1) g_offs[N_NODES] = ex + v;
        }
        __threadfence();
        __syncthreads();
        if (t == 0) atomicAdd(&g_done, 1);
    } else {
        int fb = blockIdx.x - NBLK;
        int base = fb * 2048 + t;
        int is64 = g_is64;
        int s[8], d[8], r[8];
        bool ok[8];
#pragma unroll
        for (int u = 0; u < 8; u++) {
            int e = base + u * 256;
            ok[u] = (e < N_EDGES);
            if (ok[u]) {
                s[u] = load_src(ei, e, is64);
                d[u] = load_dst(ei, e, is64);
                r[u] = g_rank[e];
            }
        }
        if (t == 0)
            while (*(volatile int*)&g_done < NBLK) __nanosleep(100);
        __syncthreads();
        __threadfence();
#pragma unroll
        for (int u = 0; u < 8; u++)
            if (ok[u]) g_esrc[g_offs[d[u]] + r[u]] = s[u];
    }
}

// ---------------- dual layer GEMM: grid (391, 2); A permuted-packed ----------------
// blockIdx.y == 0: Tout = A @ Wn (fp16, permuted)   1: Zout = A @ Ws + bias (fp32)
__global__ __launch_bounds__(256, 2)
void gemm_layer_k(const uint2* __restrict__ Apk,
                  const uint4* __restrict__ Bn,
                  const uint4* __restrict__ Bs,
                  const float* __restrict__ bias,
                  __half2* __restrict__ Tout,
                  float* __restrict__ Zout, int M) {
    constexpr int NSTEP = HIDDEN / 16;  // 8
    const int tid  = threadIdx.x;
    const int warp = tid >> 5;
    const int lane = tid & 31;
    const int g = lane >> 2, t = lane & 3;
    const int warp_m = (warp & 3) * 32;
    const int warp_n = (warp >> 2) * 64;
    const int qbase  = (warp >> 2) * 4;
    const int row_base = blockIdx.x * 128 + warp_m;
    const bool is_z = (blockIdx.y != 0);
    const uint4* __restrict__ B4 = is_z ? Bs : Bn;

    float acc[2][8][4];
#pragma unroll
    for (int mt = 0; mt < 2; mt++)
#pragma unroll
        for (int j = 0; j < 8; j++)
#pragma unroll
            for (int q = 0; q < 4; q++) acc[mt][j][q] = 0.f;

#pragma unroll
    for (int s = 0; s < NSTEP; s++) {
        uint32_t ahi[2][4], alo[2][4];
        const int pp = s * 8 + t * 2;          // permuted pair position
#pragma unroll
        for (int mt = 0; mt < 2; mt++) {
            int r0 = row_base + mt * 16 + g;
            int r1 = r0 + 8;
            uint4 z4 = make_uint4(0u, 0u, 0u, 0u);
            uint4 P0 = z4, P1 = z4;
            if (r0 < M) P0 = *(const uint4*)(Apk + (size_t)r0 * HPAIRS + pp);
            if (r1 < M) P1 = *(const uint4*)(Apk + (size_t)r1 * HPAIRS + pp);
            ahi[mt][0] = P0.x; alo[mt][0] = P0.y;   // pair 8s+t   (row r0)
            ahi[mt][2] = P0.z; alo[mt][2] = P0.w;   // pair 8s+t+4 (row r0)
            ahi[mt][1] = P1.x; alo[mt][1] = P1.y;   // pair 8s+t   (row r1)
            ahi[mt][3] = P1.z; alo[mt][3] = P1.w;   // pair 8s+t+4 (row r1)
        }
#pragma unroll
        for (int jp = 0; jp < 4; jp++) {
            uint4 b = B4[(size_t)((qbase + jp) * NSTEP + s) * 32 + lane];
#pragma unroll
            for (int mt = 0; mt < 2; mt++) {
                mma_f16(acc[mt][2 * jp],     ahi[mt], b.x, b.y);
                mma_f16(acc[mt][2 * jp],     alo[mt], b.x, b.y);
                mma_f16(acc[mt][2 * jp + 1], ahi[mt], b.z, b.w);
                mma_f16(acc[mt][2 * jp + 1], alo[mt], b.z, b.w);
            }
        }
    }

    if (is_z) {
#pragma unroll
        for (int j = 0; j < 8; j++) {
            int n0 = warp_n + j * 8 + t * 2;
            float2 bv = *(const float2*)(bias + n0);
#pragma unroll
            for (int mt = 0; mt < 2; mt++) {
                int r0 = row_base + mt * 16 + g;
                int r1 = r0 + 8;
                if (r0 < M)
                    *(float2*)(Zout + (size_t)r0 * HIDDEN + n0) =
                        make_float2(acc[mt][j][0] + bv.x, acc[mt][j][1] + bv.y);
                if (r1 < M)
                    *(float2*)(Zout + (size_t)r1 * HIDDEN + n0) =
                        make_float2(acc[mt][j][2] + bv.x, acc[mt][j][3] + bv.y);
            }
        }
    } else {
#pragma unroll
        for (int j = 0; j < 8; j++) {
            int n0 = warp_n + j * 8 + t * 2;
            int pq = permp(n0 >> 1);
#pragma unroll
            for (int mt = 0; mt < 2; mt++) {
                int r0 = row_base + mt * 16 + g;
                int r1 = r0 + 8;
                if (r0 < M)
                    Tout[(size_t)r0 * HPAIRS + pq] =
                        __floats2half2_rn(acc[mt][j][0], acc[mt][j][1]);
                if (r1 < M)
                    Tout[(size_t)r1 * HPAIRS + pq] =
                        __floats2half2_rn(acc[mt][j][2], acc[mt][j][3]);
            }
        }
    }
}

// ---------------- fused gather + epilogue (permuted t16/hpk) -----------------------
// lane handles logical pairs q0 = 8*(lane>>2)+(lane&3), q1 = q0+4 (adjacent permuted)
template <int LAST>
__global__ __launch_bounds__(256)
void gather_fused_k(const __half2* __restrict__ t16,
                    const float* __restrict__ z,
                    void* __restrict__ outv) {
    int gtid = blockIdx.x * blockDim.x + threadIdx.x;
    int node = gtid >> 5;
    if (node >= N_NODES) return;
    int lane = gtid & 31;
    int sp = lane >> 2, tp = lane & 3;
    int pp = sp * 8 + tp * 2;          // permuted position of (q0, q1)
    int q0 = sp * 8 + tp;              // logical pairs
    int c0 = q0 * 2;                   // fp32 cols [c0,c0+1] and [c0+8,c0+9]

    int start = g_offs[node];
    int end   = g_offs[node + 1];

    float4 acc = make_float4(0.f, 0.f, 0.f, 0.f);
    int e = start;
    for (; e + 4 <= end; e += 4) {
        int si[4];
#pragma unroll
        for (int u = 0; u < 4; u++) si[u] = g_esrc[e + u];
        uint2 q[4];
#pragma unroll
        for (int u = 0; u < 4; u++)
            q[u] = __ldg((const uint2*)(t16 + (size_t)si[u] * HPAIRS + pp));
#pragma unroll
        for (int u = 0; u < 4; u++) {
            float2 a = __half22float2(*(__half2*)&q[u].x);
            float2 b = __half22float2(*(__half2*)&q[u].y);
            acc.x += a.x; acc.y += a.y; acc.z += b.x; acc.w += b.y;
        }
    }
    for (; e < end; e++) {
        int s = g_esrc[e];
        uint2 q = __ldg((const uint2*)(t16 + (size_t)s * HPAIRS + pp));
        float2 a = __half22float2(*(__half2*)&q.x), b = __half22float2(*(__half2*)&q.y);
        acc.x += a.x; acc.y += a.y; acc.z += b.x; acc.w += b.y;
    }

    float inv = 1.0f / fmaxf((float)(end - start), 1.0f);
    float2 z0 = __ldg((const float2*)(z + (size_t)node * HIDDEN + c0));
    float2 z1 = __ldg((const float2*)(z + (size_t)node * HIDDEN + c0 + 8));
    float4 r;
    r.x = z0.x + acc.x * inv;
    r.y = z0.y + acc.y * inv;
    r.z = z1.x + acc.z * inv;
    r.w = z1.y + acc.w * inv;
    r.x = (r.x > 0.f) ? r.x : expm1f(r.x);
    r.y = (r.y > 0.f) ? r.y : expm1f(r.y);
    r.z = (r.z > 0.f) ? r.z : expm1f(r.z);
    r.w = (r.w > 0.f) ? r.w : expm1f(r.w);

    if (LAST) {
        float* o = (float*)outv + (size_t)node * HIDDEN;
        *(float2*)(o + c0)     = make_float2(r.x, r.y);
        *(float2*)(o + c0 + 8) = make_float2(r.z, r.w);
    } else {
        uint32_t h0, l0, h1, l1;
        split2h(make_float2(r.x, r.y), h0, l0);   // pair q0
        split2h(make_float2(r.z, r.w), h1, l1);   // pair q1
        *(uint4*)((uint2*)outv + (size_t)node * HPAIRS + pp) =
            make_uint4(h0, l0, h1, l1);
    }
}

// ---------------- launch ----------------------------------------------------------
extern "C" void kernel_launch(void* const* d_in, const int* in_sizes, int n_in,
                              void* d_out, int out_size) {
    const float* x      = (const float*)d_in[0];
    const int*   ei     = (const int*)d_in[1];
    const float* W_in   = (const float*)d_in[2];
    const float* b_in   = (const float*)d_in[3];
    const float* W_self = (const float*)d_in[4];
    const float* b_self = (const float*)d_in[5];
    const float* W_nbr  = (const float*)d_in[6];
    float*       out    = (float*)d_out;

    uint2*   hpkA; cudaGetSymbolAddress((void**)&hpkA, g_hpkA);
    uint2*   hpkB; cudaGetSymbolAddress((void**)&hpkB, g_hpkB);
    __half2* t16;  cudaGetSymbolAddress((void**)&t16,  g_t16);
    float*   z;    cudaGetSymbolAddress((void**)&z,    g_z);
    uint4*   w4;   cudaGetSymbolAddress((void**)&w4,   g_w4);

    const int M = N_NODES;

    initconv_k<<<NBLK, 256>>>(ei, W_in, W_nbr, W_self);
    gemm_in_count_k<<<GEMM_BLOCKS + NBLK, 256>>>(x, w4, b_in, hpkA, ei, M);
    scanfill_k<<<NBLK + FILL_BLOCKS, 256>>>(ei);

    const uint2* hcur = hpkA;
    for (int l = 0; l < NUM_LAYERS; l++) {
        const float* bs = b_self + (size_t)l * HIDDEN;
        const uint4* wn = w4 + 1024 + l * 2048;
        const uint4* ws = w4 + 1024 + (3 + l) * 2048;
        uint2* hnext = (hcur == hpkA) ? hpkB : hpkA;

        dim3 grid(GEMM_BLOCKS, 2);
        gemm_layer_k<<<grid, 256>>>(hcur, wn, ws, bs, t16, z, M);
        if (l == NUM_LAYERS - 1)
            gather_fused_k<1><<<(N_NODES * 32 + 255) / 256, 256>>>(t16, z, out);
        else
            gather_fused_k<0><<<(N_NODES * 32 + 255) / 256, 256>>>(t16, z, hnext);

        hcur = hnext;
    }
}

// round 16
// speedup vs baseline: 1.1462x; 1.0165x over previous
#include <cuda_runtime.h>
#include <cuda_fp16.h>
#include <cstdint>

#define N_NODES   50000
#define IN_FEAT   64
#define HIDDEN    128
#define N_EDGES   800000
#define NUM_LAYERS 3
#define NBLK      ((N_NODES + 255) / 256)   // 196
#define HPAIRS    (HIDDEN / 2)              // 64 pairs per row
#define GEMM_BLOCKS ((N_NODES + 127) / 128) // 391
#define FILL_BLOCKS 391                     // 391*2048 >= 800000

// weight fragments, uint4 {b0(Jeven),b1(Jeven),b0(Jodd),b1(Jodd)}
// W_in: 1024 u4 at 0; Wn[l]: 1024 + l*2048; Ws[l]: 1024 + (3+l)*2048
#define W4_TOTAL (1024 + 6 * 2048)          // 13312

// ---------------- scratch (device globals; no allocation allowed) ------------
__device__ __align__(128) uint2   g_hpkA[N_NODES * HPAIRS];  // permuted packed h
__device__ __align__(128) uint2   g_hpkB[N_NODES * HPAIRS];
__device__ __align__(128) __half2 g_t16 [N_NODES * HPAIRS];  // permuted t fp16
__device__ __align__(128) float   g_z   [N_NODES * HIDDEN];  // plain fp32
__device__ int g_cnt  [N_NODES];
__device__ int g_offs [N_NODES + 1];
__device__ int g_rank [N_EDGES];
__device__ int g_esrc [N_EDGES];
__device__ int g_is64;
__device__ int g_aggr  [NBLK];
__device__ int g_flagA [NBLK];
__device__ int g_prefix[NBLK];
__device__ int g_flagP;
__device__ int g_done;
__device__ __align__(256) uint4 g_w4[W4_TOTAL];

// ---------------- helpers ------------------------------------------------------
__device__ __forceinline__ uint32_t pack_h2(float x, float y) {
    __half2 h = __floats2half2_rn(x, y);
    return *(uint32_t*)&h;
}
__device__ __forceinline__ void split2h(float2 v, uint32_t& hi, uint32_t& lo) {
    __half2 h = __floats2half2_rn(v.x, v.y);
    float2 hf = __half22float2(h);
    __half2 l = __floats2half2_rn(v.x - hf.x, v.y - hf.y);
    hi = *(uint32_t*)&h;
    lo = *(uint32_t*)&l;
}
__device__ __forceinline__ void mma_f16(float* c, const uint32_t* a, uint32_t b0, uint32_t b1) {
    asm volatile(
        "mma.sync.aligned.m16n8k16.row.col.f32.f16.f16.f32 "
        "{%0,%1,%2,%3}, {%4,%5,%6,%7}, {%8,%9}, {%0,%1,%2,%3};"
        : "+f"(c[0]), "+f"(c[1]), "+f"(c[2]), "+f"(c[3])
        : "r"(a[0]), "r"(a[1]), "r"(a[2]), "r"(a[3]), "r"(b0), "r"(b1));
}
// permuted position of logical pair q: pairs (8s+t, 8s+t+4) land adjacent
__device__ __forceinline__ int permp(int q) {
    int s = q >> 3, u = q & 7;
    return 8 * s + ((u < 4) ? (u << 1) : (((u - 4) << 1) | 1));
}
__device__ __forceinline__ int load_src(const int* ei, int e, int is64) {
    return is64 ? ei[2 * e] : ei[e];
}
__device__ __forceinline__ int load_dst(const int* ei, int e, int is64) {
    return is64 ? ei[2 * (N_EDGES + e)] : ei[N_EDGES + e];
}

// ---------------- weight-fragment conversion (one uint4) ------------------------
__device__ __forceinline__ void conv_one(int idx,
                                         const float* __restrict__ W_in,
                                         const float* __restrict__ W_nbr,
                                         const float* __restrict__ W_self) {
    const float* W;
    int NSTEP, local;
    if (idx < 1024) {
        W = W_in; NSTEP = 4; local = idx;
    } else {
        int slot = (idx - 1024) / 2048;
        local = (idx - 1024) % 2048;
        NSTEP = 8;
        W = (slot < 3) ? (W_nbr  + (size_t)slot * HIDDEN * HIDDEN)
                       : (W_self + (size_t)(slot - 3) * HIDDEN * HIDDEN);
    }
    int lane = local & 31;
    int s = (local >> 5) % NSTEP;
    int q = local / (NSTEP * 32);          // J-pair 0..7
    int t = lane & 3, g = lane >> 2;
    int k0 = s * 16 + t * 2;
    int k1 = k0 + 8;
    uint32_t v[4];
#pragma unroll
    for (int h = 0; h < 2; h++) {
        int n = (2 * q + h) * 8 + g;
        v[2 * h + 0] = pack_h2(W[(size_t)k0 * HIDDEN + n], W[(size_t)(k0 + 1) * HIDDEN + n]);
        v[2 * h + 1] = pack_h2(W[(size_t)k1 * HIDDEN + n], W[(size_t)(k1 + 1) * HIDDEN + n]);
    }
    g_w4[idx] = make_uint4(v[0], v[1], v[2], v[3]);
}

// ---------------- kernel A: init (cnt/flags/detect) + weight conversion ----------
__global__ __launch_bounds__(256)
void initconv_k(const int* __restrict__ ei,
                const float* __restrict__ W_in,
                const float* __restrict__ W_nbr,
                const float* __restrict__ W_self) {
    int idx = blockIdx.x * 256 + threadIdx.x;
    if (idx < N_NODES) g_cnt[idx] = 0;
    if (idx < W4_TOTAL) conv_one(idx, W_in, W_nbr, W_self);
    if (blockIdx.x == 0) {
        int t = threadIdx.x;
        if (t < NBLK) g_flagA[t] = 0;
        if (t == 0) { g_flagP = 0; g_done = 0; }
        if (t < 32) {
            int bad = 0;
            for (int i = t; i < 256; i += 32) bad |= (ei[2 * i + 1] != 0);
            bad = __any_sync(0xFFFFFFFFu, bad);
            if (t == 0) g_is64 = !bad;
        }
    }
}

// ---------------- kernel B: input-proj GEMM (blocks < 391) + edge count ----------
__global__ __launch_bounds__(256, 2)
void gemm_in_count_k(const float* __restrict__ A,
                     const uint4* __restrict__ B4,
                     const float* __restrict__ bias,
                     uint2* __restrict__ Cpk,
                     const int* __restrict__ ei, int M) {
    __shared__ uint4 sB[1024];   // 16 KB: full W_in fragment image
    if (blockIdx.x >= GEMM_BLOCKS) {
        int cb = blockIdx.x - GEMM_BLOCKS;
        int is64 = g_is64;
        for (int e = cb * 256 + threadIdx.x; e < N_EDGES; e += NBLK * 256) {
            int d = load_dst(ei, e, is64);
            g_rank[e] = atomicAdd(&g_cnt[d], 1);
        }
        return;
    }
    constexpr int K_ = IN_FEAT, NSTEP = K_ / 16;
    const int tid  = threadIdx.x;
    const int warp = tid >> 5;
    const int lane = tid & 31;
    const int g = lane >> 2, t = lane & 3;
    const int warp_m = (warp & 3) * 32;
    const int warp_n = (warp >> 2) * 64;
    const int qbase  = (warp >> 2) * 4;       // J-pair base
    const int row_base = blockIdx.x * 128 + warp_m;

    // stage B once (4x fewer global B reads than in-loop)
#pragma unroll
    for (int i = tid; i < 1024; i += 256) sB[i] = B4[i];
    __syncthreads();

    float acc[2][8][4];
#pragma unroll
    for (int mt = 0; mt < 2; mt++)
#pragma unroll
        for (int j = 0; j < 8; j++)
#pragma unroll
            for (int q = 0; q < 4; q++) acc[mt][j][q] = 0.f;

#pragma unroll
    for (int s = 0; s < NSTEP; s++) {
        uint32_t ahi[2][4], alo[2][4];
        const int c0 = s * 16 + t * 2;
#pragma unroll
        for (int mt = 0; mt < 2; mt++) {
            int r0 = row_base + mt * 16 + g;
            int r1 = r0 + 8;
            float2 v00 = make_float2(0.f, 0.f), v10 = v00, v01 = v00, v11 = v00;
            if (r0 < M) {
                v00 = *(const float2*)(A + (size_t)r0 * K_ + c0);
                v01 = *(const float2*)(A + (size_t)r0 * K_ + c0 + 8);
            }
            if (r1 < M) {
                v10 = *(const float2*)(A + (size_t)r1 * K_ + c0);
                v11 = *(const float2*)(A + (size_t)r1 * K_ + c0 + 8);
            }
            split2h(v00, ahi[mt][0], alo[mt][0]);
            split2h(v10, ahi[mt][1], alo[mt][1]);
            split2h(v01, ahi[mt][2], alo[mt][2]);
            split2h(v11, ahi[mt][3], alo[mt][3]);
        }
#pragma unroll
        for (int jp = 0; jp < 4; jp++) {
            uint4 b = sB[((qbase + jp) * NSTEP + s) * 32 + lane];
#pragma unroll
            for (int mt = 0; mt < 2; mt++) {
                mma_f16(acc[mt][2 * jp],     ahi[mt], b.x, b.y);
                mma_f16(acc[mt][2 * jp],     alo[mt], b.x, b.y);
                mma_f16(acc[mt][2 * jp + 1], ahi[mt], b.z, b.w);
                mma_f16(acc[mt][2 * jp + 1], alo[mt], b.z, b.w);
            }
        }
    }
#pragma unroll
    for (int j = 0; j < 8; j++) {
        int n0 = warp_n + j * 8 + t * 2;
        int pq = permp(n0 >> 1);
        float2 bv = *(const float2*)(bias + n0);
#pragma unroll
        for (int mt = 0; mt < 2; mt++) {
            int r0 = row_base + mt * 16 + g;
            int r1 = r0 + 8;
            uint32_t h0, l0, h1, l1;
            split2h(make_float2(acc[mt][j][0] + bv.x, acc[mt][j][1] + bv.y), h0, l0);
            split2h(make_float2(acc[mt][j][2] + bv.x, acc[mt][j][3] + bv.y), h1, l1);
            if (r0 < M) Cpk[(size_t)r0 * HPAIRS + pq] = make_uint2(h0, l0);
            if (r1 < M) Cpk[(size_t)r1 * HPAIRS + pq] = make_uint2(h1, l1);
        }
    }
}

// ---------------- kernel C: scan (blocks < 196) + fill (rest) ---------------------
__global__ __launch_bounds__(256)
void scanfill_k(const int* __restrict__ ei) {
    const int t = threadIdx.x;
    if (blockIdx.x < NBLK) {
        __shared__ int sh[256];
        __shared__ int sa[256];
        const int bid = blockIdx.x;
        const int idx = bid * 256 + t;

        int v = (idx < N_NODES) ? g_cnt[idx] : 0;
        sh[t] = v;
        __syncthreads();
        for (int d = 1; d < 256; d <<= 1) {
            int n = (t >= d) ? sh[t - d] : 0;
            __syncthreads();
            sh[t] += n;
            __syncthreads();
        }
        if (t == 0) {
            g_aggr[bid] = sh[255];
            __threadfence();
            *(volatile int*)&g_flagA[bid] = 1;
        }
        if (bid == 0) {
            for (int i = t; i < NBLK; i += 256)
                while (*(volatile int*)&g_flagA[i] == 0) __nanosleep(50);
            __syncthreads();
            int a = 0;
            if (t < NBLK) a = g_aggr[t];
            sa[t] = a;
            __syncthreads();
            for (int d = 1; d < 256; d <<= 1) {
                int n = (t >= d) ? sa[t - d] : 0;
                __syncthreads();
                sa[t] += n;
                __syncthreads();
            }
            if (t < NBLK) g_prefix[t] = sa[t] - a;
            __threadfence();
            __syncthreads();
            if (t == 0) *(volatile int*)&g_flagP = 1;
        }
        if (t == 0)
            while (*(volatile int*)&g_flagP == 0) __nanosleep(50);
        __syncthreads();
        __threadfence();

        int ex = g_prefix[bid] + sh[t] - v;
        if (idx < N_NODES) {
            g_offs[idx] = ex;
            if (idx == N_NODES - 1) g_offs[N_NODES] = ex + v;
        }
        __threadfence();
        __syncthreads();
        if (t == 0) atomicAdd(&g_done, 1);
    } else {
        int fb = blockIdx.x - NBLK;
        int base = fb * 2048 + t;
        int is64 = g_is64;
        int s[8], d[8], r[8];
        bool ok[8];
#pragma unroll
        for (int u = 0; u < 8; u++) {
            int e = base + u * 256;
            ok[u] = (e < N_EDGES);
            if (ok[u]) {
                s[u] = load_src(ei, e, is64);
                d[u] = load_dst(ei, e, is64);
                r[u] = g_rank[e];
            }
        }
        if (t == 0)
            while (*(volatile int*)&g_done < NBLK) __nanosleep(100);
        __syncthreads();
        __threadfence();
#pragma unroll
        for (int u = 0; u < 8; u++)
            if (ok[u]) g_esrc[g_offs[d[u]] + r[u]] = s[u];
    }
}

// ---------------- dual layer GEMM: grid (391, 2); A permuted-packed ----------------
// blockIdx.y == 0: Tout = A @ Wn (fp16, permuted)   1: Zout = A @ Ws + bias (fp32)
__global__ __launch_bounds__(256, 2)
void gemm_layer_k(const uint2* __restrict__ Apk,
                  const uint4* __restrict__ Bn,
                  const uint4* __restrict__ Bs,
                  const float* __restrict__ bias,
                  __half2* __restrict__ Tout,
                  float* __restrict__ Zout, int M) {
    constexpr int NSTEP = HIDDEN / 16;  // 8
    __shared__ uint4 sB[2048];          // 32 KB: full weight fragment image
    const int tid  = threadIdx.x;
    const int warp = tid >> 5;
    const int lane = tid & 31;
    const int g = lane >> 2, t = lane & 3;
    const int warp_m = (warp & 3) * 32;
    const int warp_n = (warp >> 2) * 64;
    const int qbase  = (warp >> 2) * 4;
    const int row_base = blockIdx.x * 128 + warp_m;
    const bool is_z = (blockIdx.y != 0);
    const uint4* __restrict__ B4 = is_z ? Bs : Bn;

    // stage B once (4x fewer global B reads than in-loop)
#pragma unroll
    for (int i = tid; i < 2048; i += 256) sB[i] = B4[i];
    __syncthreads();

    float acc[2][8][4];
#pragma unroll
    for (int mt = 0; mt < 2; mt++)
#pragma unroll
        for (int j = 0; j < 8; j++)
#pragma unroll
            for (int q = 0; q < 4; q++) acc[mt][j][q] = 0.f;

#pragma unroll
    for (int s = 0; s < NSTEP; s++) {
        uint32_t ahi[2][4], alo[2][4];
        const int pp = s * 8 + t * 2;          // permuted pair position
#pragma unroll
        for (int mt = 0; mt < 2; mt++) {
            int r0 = row_base + mt * 16 + g;
            int r1 = r0 + 8;
            uint4 z4 = make_uint4(0u, 0u, 0u, 0u);
            uint4 P0 = z4, P1 = z4;
            if (r0 < M) P0 = *(const uint4*)(Apk + (size_t)r0 * HPAIRS + pp);
            if (r1 < M) P1 = *(const uint4*)(Apk + (size_t)r1 * HPAIRS + pp);
            ahi[mt][0] = P0.x; alo[mt][0] = P0.y;
            ahi[mt][2] = P0.z; alo[mt][2] = P0.w;
            ahi[mt][1] = P1.x; alo[mt][1] = P1.y;
            ahi[mt][3] = P1.z; alo[mt][3] = P1.w;
        }
#pragma unroll
        for (int jp = 0; jp < 4; jp++) {
            uint4 b = sB[((qbase + jp) * NSTEP + s) * 32 + lane];
#pragma unroll
            for (int mt = 0; mt < 2; mt++) {
                mma_f16(acc[mt][2 * jp],     ahi[mt], b.x, b.y);
                mma_f16(acc[mt][2 * jp],     alo[mt], b.x, b.y);
                mma_f16(acc[mt][2 * jp + 1], ahi[mt], b.z, b.w);
                mma_f16(acc[mt][2 * jp + 1], alo[mt], b.z, b.w);
            }
        }
    }

    if (is_z) {
#pragma unroll
        for (int j = 0; j < 8; j++) {
            int n0 = warp_n + j * 8 + t * 2;
            float2 bv = *(const float2*)(bias + n0);
#pragma unroll
            for (int mt = 0; mt < 2; mt++) {
                int r0 = row_base + mt * 16 + g;
                int r1 = r0 + 8;
                if (r0 < M)
                    *(float2*)(Zout + (size_t)r0 * HIDDEN + n0) =
                        make_float2(acc[mt][j][0] + bv.x, acc[mt][j][1] + bv.y);
                if (r1 < M)
                    *(float2*)(Zout + (size_t)r1 * HIDDEN + n0) =
                        make_float2(acc[mt][j][2] + bv.x, acc[mt][j][3] + bv.y);
            }
        }
    } else {
#pragma unroll
        for (int j = 0; j < 8; j++) {
            int n0 = warp_n + j * 8 + t * 2;
            int pq = permp(n0 >> 1);
#pragma unroll
            for (int mt = 0; mt < 2; mt++) {
                int r0 = row_base + mt * 16 + g;
                int r1 = r0 + 8;
                if (r0 < M)
                    Tout[(size_t)r0 * HPAIRS + pq] =
                        __floats2half2_rn(acc[mt][j][0], acc[mt][j][1]);
                if (r1 < M)
                    Tout[(size_t)r1 * HPAIRS + pq] =
                        __floats2half2_rn(acc[mt][j][2], acc[mt][j][3]);
            }
        }
    }
}

// ---------------- fused gather + epilogue (permuted t16/hpk) -----------------------
// lane handles logical pairs q0 = 8*(lane>>2)+(lane&3), q1 = q0+4 (adjacent permuted)
template <int LAST>
__global__ __launch_bounds__(256)
void gather_fused_k(const __half2* __restrict__ t16,
                    const float* __restrict__ z,
                    void* __restrict__ outv) {
    int gtid = blockIdx.x * blockDim.x + threadIdx.x;
    int node = gtid >> 5;
    if (node >= N_NODES) return;
    int lane = gtid & 31;
    int sp = lane >> 2, tp = lane & 3;
    int pp = sp * 8 + tp * 2;          // permuted position of (q0, q1)
    int q0 = sp * 8 + tp;              // logical pairs
    int c0 = q0 * 2;                   // fp32 cols [c0,c0+1] and [c0+8,c0+9]

    int start = g_offs[node];
    int end   = g_offs[node + 1];

    float4 acc = make_float4(0.f, 0.f, 0.f, 0.f);
    int e = start;
    for (; e + 4 <= end; e += 4) {
        int si[4];
#pragma unroll
        for (int u = 0; u < 4; u++) si[u] = g_esrc[e + u];
        uint2 q[4];
#pragma unroll
        for (int u = 0; u < 4; u++)
            q[u] = __ldg((const uint2*)(t16 + (size_t)si[u] * HPAIRS + pp));
#pragma unroll
        for (int u = 0; u < 4; u++) {
            float2 a = __half22float2(*(__half2*)&q[u].x);
            float2 b = __half22float2(*(__half2*)&q[u].y);
            acc.x += a.x; acc.y += a.y; acc.z += b.x; acc.w += b.y;
        }
    }
    for (; e < end; e++) {
        int s = g_esrc[e];
        uint2 q = __ldg((const uint2*)(t16 + (size_t)s * HPAIRS + pp));
        float2 a = __half22float2(*(__half2*)&q.x), b = __half22float2(*(__half2*)&q.y);
        acc.x += a.x; acc.y += a.y; acc.z += b.x; acc.w += b.y;
    }

    float inv = 1.0f / fmaxf((float)(end - start), 1.0f);
    float2 z0 = __ldg((const float2*)(z + (size_t)node * HIDDEN + c0));
    float2 z1 = __ldg((const float2*)(z + (size_t)node * HIDDEN + c0 + 8));
    float4 r;
    r.x = z0.x + acc.x * inv;
    r.y = z0.y + acc.y * inv;
    r.z = z1.x + acc.z * inv;
    r.w = z1.y + acc.w * inv;
    r.x = (r.x > 0.f) ? r.x : expm1f(r.x);
    r.y = (r.y > 0.f) ? r.y : expm1f(r.y);
    r.z = (r.z > 0.f) ? r.z : expm1f(r.z);
    r.w = (r.w > 0.f) ? r.w : expm1f(r.w);

    if (LAST) {
        float* o = (float*)outv + (size_t)node * HIDDEN;
        *(float2*)(o + c0)     = make_float2(r.x, r.y);
        *(float2*)(o + c0 + 8) = make_float2(r.z, r.w);
    } else {
        uint32_t h0, l0, h1, l1;
        split2h(make_float2(r.x, r.y), h0, l0);   // pair q0
        split2h(make_float2(r.z, r.w), h1, l1);   // pair q1
        *(uint4*)((uint2*)outv + (size_t)node * HPAIRS + pp) =
            make_uint4(h0, l0, h1, l1);
    }
}

// ---------------- launch ----------------------------------------------------------
extern "C" void kernel_launch(void* const* d_in, const int* in_sizes, int n_in,
                              void* d_out, int out_size) {
    const float* x      = (const float*)d_in[0];
    const int*   ei     = (const int*)d_in[1];
    const float* W_in   = (const float*)d_in[2];
    const float* b_in   = (const float*)d_in[3];
    const float* W_self = (const float*)d_in[4];
    const float* b_self = (const float*)d_in[5];
    const float* W_nbr  = (const float*)d_in[6];
    float*       out    = (float*)d_out;

    uint2*   hpkA; cudaGetSymbolAddress((void**)&hpkA, g_hpkA);
    uint2*   hpkB; cudaGetSymbolAddress((void**)&hpkB, g_hpkB);
    __half2* t16;  cudaGetSymbolAddress((void**)&t16,  g_t16);
    float*   z;    cudaGetSymbolAddress((void**)&z,    g_z);
    uint4*   w4;   cudaGetSymbolAddress((void**)&w4,   g_w4);

    const int M = N_NODES;

    initconv_k<<<NBLK, 256>>>(ei, W_in, W_nbr, W_self);
    gemm_in_count_k<<<GEMM_BLOCKS + NBLK, 256>>>(x, w4, b_in, hpkA, ei, M);
    scanfill_k<<<NBLK + FILL_BLOCKS, 256>>>(ei);

    const uint2* hcur = hpkA;
    for (int l = 0; l < NUM_LAYERS; l++) {
        const float* bs = b_self + (size_t)l * HIDDEN;
        const uint4* wn = w4 + 1024 + l * 2048;
        const uint4* ws = w4 + 1024 + (3 + l) * 2048;
        uint2* hnext = (hcur == hpkA) ? hpkB : hpkA;

        dim3 grid(GEMM_BLOCKS, 2);
        gemm_layer_k<<<grid, 256>>>(hcur, wn, ws, bs, t16, z, M);
        if (l == NUM_LAYERS - 1)
            gather_fused_k<1><<<(N_NODES * 32 + 255) / 256, 256>>>(t16, z, out);
        else
            gather_fused_k<0><<<(N_NODES * 32 + 255) / 256, 256>>>(t16, z, hnext);

        hcur = hnext;
    }
}

// round 17
// speedup vs baseline: 1.1503x; 1.0036x over previous
#include <cuda_runtime.h>
#include <cuda_fp16.h>
#include <cstdint>

#define N_NODES   50000
#define IN_FEAT   64
#define HIDDEN    128
#define N_EDGES   800000
#define NUM_LAYERS 3
#define NBLK      ((N_NODES + 255) / 256)   // 196
#define HPAIRS    (HIDDEN / 2)              // 64 pairs per row
#define GEMM_BLOCKS ((N_NODES + 127) / 128) // 391
#define FILL_BLOCKS 391                     // 391*2048 >= 800000

// weight fragments, uint4 {b0(Jeven),b1(Jeven),b0(Jodd),b1(Jodd)}
// W_in: 1024 u4 at 0; Wn[l]: 1024 + l*2048; Ws[l]: 1024 + (3+l)*2048
#define W4_TOTAL (1024 + 6 * 2048)          // 13312

// ---------------- scratch (device globals; no allocation allowed) ------------
__device__ __align__(128) uint2   g_hpkA[N_NODES * HPAIRS];  // permuted packed h
__device__ __align__(128) uint2   g_hpkB[N_NODES * HPAIRS];
__device__ __align__(128) __half2 g_t16 [N_NODES * HPAIRS];  // permuted t fp16
__device__ __align__(128) float   g_z   [N_NODES * HIDDEN];  // plain fp32
__device__ int g_cnt  [N_NODES];
__device__ int g_offs [N_NODES + 1];
__device__ int g_rank [N_EDGES];
__device__ int g_esrc [N_EDGES];
__device__ int g_is64;
__device__ int g_aggr  [NBLK];
__device__ int g_flagA [NBLK];
__device__ int g_prefix[NBLK];
__device__ int g_flagP;
__device__ int g_done;
__device__ __align__(256) uint4 g_w4[W4_TOTAL];

// ---------------- helpers ------------------------------------------------------
__device__ __forceinline__ uint32_t pack_h2(float x, float y) {
    __half2 h = __floats2half2_rn(x, y);
    return *(uint32_t*)&h;
}
__device__ __forceinline__ void split2h(float2 v, uint32_t& hi, uint32_t& lo) {
    __half2 h = __floats2half2_rn(v.x, v.y);
    float2 hf = __half22float2(h);
    __half2 l = __floats2half2_rn(v.x - hf.x, v.y - hf.y);
    hi = *(uint32_t*)&h;
    lo = *(uint32_t*)&l;
}
__device__ __forceinline__ void mma_f16(float* c, const uint32_t* a, uint32_t b0, uint32_t b1) {
    asm volatile(
        "mma.sync.aligned.m16n8k16.row.col.f32.f16.f16.f32 "
        "{%0,%1,%2,%3}, {%4,%5,%6,%7}, {%8,%9}, {%0,%1,%2,%3};"
        : "+f"(c[0]), "+f"(c[1]), "+f"(c[2]), "+f"(c[3])
        : "r"(a[0]), "r"(a[1]), "r"(a[2]), "r"(a[3]), "r"(b0), "r"(b1));
}
// permuted position of logical pair q: pairs (8s+t, 8s+t+4) land adjacent
__device__ __forceinline__ int permp(int q) {
    int s = q >> 3, u = q & 7;
    return 8 * s + ((u < 4) ? (u << 1) : (((u - 4) << 1) | 1));
}
__device__ __forceinline__ int load_src(const int* ei, int e, int is64) {
    return is64 ? ei[2 * e] : ei[e];
}
__device__ __forceinline__ int load_dst(const int* ei, int e, int is64) {
    return is64 ? ei[2 * (N_EDGES + e)] : ei[N_EDGES + e];
}

// ---------------- weight-fragment conversion (one uint4) ------------------------
__device__ __forceinline__ void conv_one(int idx,
                                         const float* __restrict__ W_in,
                                         const float* __restrict__ W_nbr,
                                         const float* __restrict__ W_self) {
    const float* W;
    int NSTEP, local;
    if (idx < 1024) {
        W = W_in; NSTEP = 4; local = idx;
    } else {
        int slot = (idx - 1024) / 2048;
        local = (idx - 1024) % 2048;
        NSTEP = 8;
        W = (slot < 3) ? (W_nbr  + (size_t)slot * HIDDEN * HIDDEN)
                       : (W_self + (size_t)(slot - 3) * HIDDEN * HIDDEN);
    }
    int lane = local & 31;
    int s = (local >> 5) % NSTEP;
    int q = local / (NSTEP * 32);          // J-pair 0..7
    int t = lane & 3, g = lane >> 2;
    int k0 = s * 16 + t * 2;
    int k1 = k0 + 8;
    uint32_t v[4];
#pragma unroll
    for (int h = 0; h < 2; h++) {
        int n = (2 * q + h) * 8 + g;
        v[2 * h + 0] = pack_h2(W[(size_t)k0 * HIDDEN + n], W[(size_t)(k0 + 1) * HIDDEN + n]);
        v[2 * h + 1] = pack_h2(W[(size_t)k1 * HIDDEN + n], W[(size_t)(k1 + 1) * HIDDEN + n]);
    }
    g_w4[idx] = make_uint4(v[0], v[1], v[2], v[3]);
}

// ---------------- kernel A: init (cnt/flags/detect) + weight conversion ----------
__global__ __launch_bounds__(256)
void initconv_k(const int* __restrict__ ei,
                const float* __restrict__ W_in,
                const float* __restrict__ W_nbr,
                const float* __restrict__ W_self) {
    int idx = blockIdx.x * 256 + threadIdx.x;
    if (idx < N_NODES) g_cnt[idx] = 0;
    if (idx < W4_TOTAL) conv_one(idx, W_in, W_nbr, W_self);
    if (blockIdx.x == 0) {
        int t = threadIdx.x;
        if (t < NBLK) g_flagA[t] = 0;
        if (t == 0) { g_flagP = 0; g_done = 0; }
        if (t < 32) {
            int bad = 0;
            for (int i = t; i < 256; i += 32) bad |= (ei[2 * i + 1] != 0);
            bad = __any_sync(0xFFFFFFFFu, bad);
            if (t == 0) g_is64 = !bad;
        }
    }
}

// ---------------- kernel B: input-proj GEMM (blocks < 391) + edge count ----------
__global__ __launch_bounds__(256, 2)
void gemm_in_count_k(const float* __restrict__ A,
                     const uint4* __restrict__ B4,
                     const float* __restrict__ bias,
                     uint2* __restrict__ Cpk,
                     const int* __restrict__ ei, int M) {
    __shared__ uint4 sB[1024];   // 16 KB: full W_in fragment image
    if (blockIdx.x >= GEMM_BLOCKS) {
        int cb = blockIdx.x - GEMM_BLOCKS;
        int is64 = g_is64;
        for (int e = cb * 256 + threadIdx.x; e < N_EDGES; e += NBLK * 256) {
            int d = load_dst(ei, e, is64);
            g_rank[e] = atomicAdd(&g_cnt[d], 1);
        }
        return;
    }
    constexpr int K_ = IN_FEAT, NSTEP = K_ / 16;
    const int tid  = threadIdx.x;
    const int warp = tid >> 5;
    const int lane = tid & 31;
    const int g = lane >> 2, t = lane & 3;
    const int warp_m = (warp & 3) * 32;
    const int warp_n = (warp >> 2) * 64;
    const int qbase  = (warp >> 2) * 4;       // J-pair base
    const int row_base = blockIdx.x * 128 + warp_m;

#pragma unroll
    for (int i = tid; i < 1024; i += 256) sB[i] = B4[i];
    __syncthreads();

    float acc[2][8][4];
#pragma unroll
    for (int mt = 0; mt < 2; mt++)
#pragma unroll
        for (int j = 0; j < 8; j++)
#pragma unroll
            for (int q = 0; q < 4; q++) acc[mt][j][q] = 0.f;

#pragma unroll
    for (int s = 0; s < NSTEP; s++) {
        uint32_t ahi[2][4], alo[2][4];
        const int c0 = s * 16 + t * 2;
#pragma unroll
        for (int mt = 0; mt < 2; mt++) {
            int r0 = row_base + mt * 16 + g;
            int r1 = r0 + 8;
            float2 v00 = make_float2(0.f, 0.f), v10 = v00, v01 = v00, v11 = v00;
            if (r0 < M) {
                v00 = *(const float2*)(A + (size_t)r0 * K_ + c0);
                v01 = *(const float2*)(A + (size_t)r0 * K_ + c0 + 8);
            }
            if (r1 < M) {
                v10 = *(const float2*)(A + (size_t)r1 * K_ + c0);
                v11 = *(const float2*)(A + (size_t)r1 * K_ + c0 + 8);
            }
            split2h(v00, ahi[mt][0], alo[mt][0]);
            split2h(v10, ahi[mt][1], alo[mt][1]);
            split2h(v01, ahi[mt][2], alo[mt][2]);
            split2h(v11, ahi[mt][3], alo[mt][3]);
        }
        uint4 b[4];
#pragma unroll
        for (int jp = 0; jp < 4; jp++)
            b[jp] = sB[((qbase + jp) * NSTEP + s) * 32 + lane];
        // hi pass: 16 independent MMAs
#pragma unroll
        for (int jp = 0; jp < 4; jp++)
#pragma unroll
            for (int mt = 0; mt < 2; mt++) {
                mma_f16(acc[mt][2 * jp],     ahi[mt], b[jp].x, b[jp].y);
                mma_f16(acc[mt][2 * jp + 1], ahi[mt], b[jp].z, b[jp].w);
            }
        // lo pass: 16 independent MMAs (each acc: hi then lo — order unchanged)
#pragma unroll
        for (int jp = 0; jp < 4; jp++)
#pragma unroll
            for (int mt = 0; mt < 2; mt++) {
                mma_f16(acc[mt][2 * jp],     alo[mt], b[jp].x, b[jp].y);
                mma_f16(acc[mt][2 * jp + 1], alo[mt], b[jp].z, b[jp].w);
            }
    }
#pragma unroll
    for (int j = 0; j < 8; j++) {
        int n0 = warp_n + j * 8 + t * 2;
        int pq = permp(n0 >> 1);
        float2 bv = *(const float2*)(bias + n0);
#pragma unroll
        for (int mt = 0; mt < 2; mt++) {
            int r0 = row_base + mt * 16 + g;
            int r1 = r0 + 8;
            uint32_t h0, l0, h1, l1;
            split2h(make_float2(acc[mt][j][0] + bv.x, acc[mt][j][1] + bv.y), h0, l0);
            split2h(make_float2(acc[mt][j][2] + bv.x, acc[mt][j][3] + bv.y), h1, l1);
            if (r0 < M) Cpk[(size_t)r0 * HPAIRS + pq] = make_uint2(h0, l0);
            if (r1 < M) Cpk[(size_t)r1 * HPAIRS + pq] = make_uint2(h1, l1);
        }
    }
}

// ---------------- kernel C: scan (blocks < 196) + fill (rest) ---------------------
__global__ __launch_bounds__(256)
void scanfill_k(const int* __restrict__ ei) {
    const int t = threadIdx.x;
    if (blockIdx.x < NBLK) {
        __shared__ int sh[256];
        __shared__ int sa[256];
        const int bid = blockIdx.x;
        const int idx = bid * 256 + t;

        int v = (idx < N_NODES) ? g_cnt[idx] : 0;
        sh[t] = v;
        __syncthreads();
        for (int d = 1; d < 256; d <<= 1) {
            int n = (t >= d) ? sh[t - d] : 0;
            __syncthreads();
            sh[t] += n;
            __syncthreads();
        }
        if (t == 0) {
            g_aggr[bid] = sh[255];
            __threadfence();
            *(volatile int*)&g_flagA[bid] = 1;
        }
        if (bid == 0) {
            for (int i = t; i < NBLK; i += 256)
                while (*(volatile int*)&g_flagA[i] == 0) __nanosleep(50);
            __syncthreads();
            int a = 0;
            if (t < NBLK) a = g_aggr[t];
            sa[t] = a;
            __syncthreads();
            for (int d = 1; d < 256; d <<= 1) {
                int n = (t >= d) ? sa[t - d] : 0;
                __syncthreads();
                sa[t] += n;
                __syncthreads();
            }
            if (t < NBLK) g_prefix[t] = sa[t] - a;
            __threadfence();
            __syncthreads();
            if (t == 0) *(volatile int*)&g_flagP = 1;
        }
        if (t == 0)
            while (*(volatile int*)&g_flagP == 0) __nanosleep(50);
        __syncthreads();
        __threadfence();

        int ex = g_prefix[bid] + sh[t] - v;
        if (idx < N_NODES) {
            g_offs[idx] = ex;
            if (idx == N_NODES - 1) g_offs[N_NODES] = ex + v;
        }
        __threadfence();
        __syncthreads();
        if (t == 0) atomicAdd(&g_done, 1);
    } else {
        int fb = blockIdx.x - NBLK;
        int base = fb * 2048 + t;
        int is64 = g_is64;
        int s[8], d[8], r[8];
        bool ok[8];
#pragma unroll
        for (int u = 0; u < 8; u++) {
            int e = base + u * 256;
            ok[u] = (e < N_EDGES);
            if (ok[u]) {
                s[u] = load_src(ei, e, is64);
                d[u] = load_dst(ei, e, is64);
                r[u] = g_rank[e];
            }
        }
        if (t == 0)
            while (*(volatile int*)&g_done < NBLK) __nanosleep(100);
        __syncthreads();
        __threadfence();
#pragma unroll
        for (int u = 0; u < 8; u++)
            if (ok[u]) g_esrc[g_offs[d[u]] + r[u]] = s[u];
    }
}

// ---------------- dual layer GEMM: grid (391, 2); A permuted-packed ----------------
// blockIdx.y == 0: Tout = A @ Wn (fp16, permuted)   1: Zout = A @ Ws + bias (fp32)
__global__ __launch_bounds__(256, 2)
void gemm_layer_k(const uint2* __restrict__ Apk,
                  const uint4* __restrict__ Bn,
                  const uint4* __restrict__ Bs,
                  const float* __restrict__ bias,
                  __half2* __restrict__ Tout,
                  float* __restrict__ Zout, int M) {
    constexpr int NSTEP = HIDDEN / 16;  // 8
    __shared__ uint4 sB[2048];          // 32 KB: full weight fragment image
    const int tid  = threadIdx.x;
    const int warp = tid >> 5;
    const int lane = tid & 31;
    const int g = lane >> 2, t = lane & 3;
    const int warp_m = (warp & 3) * 32;
    const int warp_n = (warp >> 2) * 64;
    const int qbase  = (warp >> 2) * 4;
    const int row_base = blockIdx.x * 128 + warp_m;
    const bool is_z = (blockIdx.y != 0);
    const uint4* __restrict__ B4 = is_z ? Bs : Bn;

#pragma unroll
    for (int i = tid; i < 2048; i += 256) sB[i] = B4[i];
    __syncthreads();

    float acc[2][8][4];
#pragma unroll
    for (int mt = 0; mt < 2; mt++)
#pragma unroll
        for (int j = 0; j < 8; j++)
#pragma unroll
            for (int q = 0; q < 4; q++) acc[mt][j][q] = 0.f;

#pragma unroll
    for (int s = 0; s < NSTEP; s++) {
        uint32_t ahi[2][4], alo[2][4];
        const int pp = s * 8 + t * 2;          // permuted pair position
#pragma unroll
        for (int mt = 0; mt < 2; mt++) {
            int r0 = row_base + mt * 16 + g;
            int r1 = r0 + 8;
            uint4 z4 = make_uint4(0u, 0u, 0u, 0u);
            uint4 P0 = z4, P1 = z4;
            if (r0 < M) P0 = *(const uint4*)(Apk + (size_t)r0 * HPAIRS + pp);
            if (r1 < M) P1 = *(const uint4*)(Apk + (size_t)r1 * HPAIRS + pp);
            ahi[mt][0] = P0.x; alo[mt][0] = P0.y;
            ahi[mt][2] = P0.z; alo[mt][2] = P0.w;
            ahi[mt][1] = P1.x; alo[mt][1] = P1.y;
            ahi[mt][3] = P1.z; alo[mt][3] = P1.w;
        }
        uint4 b[4];
#pragma unroll
        for (int jp = 0; jp < 4; jp++)
            b[jp] = sB[((qbase + jp) * NSTEP + s) * 32 + lane];
        // hi pass: 16 independent MMAs
#pragma unroll
        for (int jp = 0; jp < 4; jp++)
#pragma unroll
            for (int mt = 0; mt < 2; mt++) {
                mma_f16(acc[mt][2 * jp],     ahi[mt], b[jp].x, b[jp].y);
                mma_f16(acc[mt][2 * jp + 1], ahi[mt], b[jp].z, b[jp].w);
            }
        // lo pass: 16 independent MMAs (each acc: hi then lo — order unchanged)
#pragma unroll
        for (int jp = 0; jp < 4; jp++)
#pragma unroll
            for (int mt = 0; mt < 2; mt++) {
                mma_f16(acc[mt][2 * jp],     alo[mt], b[jp].x, b[jp].y);
                mma_f16(acc[mt][2 * jp + 1], alo[mt], b[jp].z, b[jp].w);
            }
    }

    if (is_z) {
#pragma unroll
        for (int j = 0; j < 8; j++) {
            int n0 = warp_n + j * 8 + t * 2;
            float2 bv = *(const float2*)(bias + n0);
#pragma unroll
            for (int mt = 0; mt < 2; mt++) {
                int r0 = row_base + mt * 16 + g;
                int r1 = r0 + 8;
                if (r0 < M)
                    *(float2*)(Zout + (size_t)r0 * HIDDEN + n0) =
                        make_float2(acc[mt][j][0] + bv.x, acc[mt][j][1] + bv.y);
                if (r1 < M)
                    *(float2*)(Zout + (size_t)r1 * HIDDEN + n0) =
                        make_float2(acc[mt][j][2] + bv.x, acc[mt][j][3] + bv.y);
            }
        }
    } else {
#pragma unroll
        for (int j = 0; j < 8; j++) {
            int n0 = warp_n + j * 8 + t * 2;
            int pq = permp(n0 >> 1);
#pragma unroll
            for (int mt = 0; mt < 2; mt++) {
                int r0 = row_base + mt * 16 + g;
                int r1 = r0 + 8;
                if (r0 < M)
                    Tout[(size_t)r0 * HPAIRS + pq] =
                        __floats2half2_rn(acc[mt][j][0], acc[mt][j][1]);
                if (r1 < M)
                    Tout[(size_t)r1 * HPAIRS + pq] =
                        __floats2half2_rn(acc[mt][j][2], acc[mt][j][3]);
            }
        }
    }
}

// ---------------- fused gather + epilogue (permuted t16/hpk) -----------------------
// lane handles logical pairs q0 = 8*(lane>>2)+(lane&3), q1 = q0+4 (adjacent permuted)
template <int LAST>
__global__ __launch_bounds__(256)
void gather_fused_k(const __half2* __restrict__ t16,
                    const float* __restrict__ z,
                    void* __restrict__ outv) {
    int gtid = blockIdx.x * blockDim.x + threadIdx.x;
    int node = gtid >> 5;
    if (node >= N_NODES) return;
    int lane = gtid & 31;
    int sp = lane >> 2, tp = lane & 3;
    int pp = sp * 8 + tp * 2;          // permuted position of (q0, q1)
    int q0 = sp * 8 + tp;              // logical pairs
    int c0 = q0 * 2;                   // fp32 cols [c0,c0+1] and [c0+8,c0+9]

    int start = g_offs[node];
    int end   = g_offs[node + 1];

    float4 acc = make_float4(0.f, 0.f, 0.f, 0.f);
    int e = start;
    for (; e + 4 <= end; e += 4) {
        int si[4];
#pragma unroll
        for (int u = 0; u < 4; u++) si[u] = g_esrc[e + u];
        uint2 q[4];
#pragma unroll
        for (int u = 0; u < 4; u++)
            q[u] = __ldg((const uint2*)(t16 + (size_t)si[u] * HPAIRS + pp));
#pragma unroll
        for (int u = 0; u < 4; u++) {
            float2 a = __half22float2(*(__half2*)&q[u].x);
            float2 b = __half22float2(*(__half2*)&q[u].y);
            acc.x += a.x; acc.y += a.y; acc.z += b.x; acc.w += b.y;
        }
    }
    for (; e < end; e++) {
        int s = g_esrc[e];
        uint2 q = __ldg((const uint2*)(t16 + (size_t)s * HPAIRS + pp));
        float2 a = __half22float2(*(__half2*)&q.x), b = __half22float2(*(__half2*)&q.y);
        acc.x += a.x; acc.y += a.y; acc.z += b.x; acc.w += b.y;
    }

    float inv = 1.0f / fmaxf((float)(end - start), 1.0f);
    float2 z0 = __ldg((const float2*)(z + (size_t)node * HIDDEN + c0));
    float2 z1 = __ldg((const float2*)(z + (size_t)node * HIDDEN + c0 + 8));
    float4 r;
    r.x = z0.x + acc.x * inv;
    r.y = z0.y + acc.y * inv;
    r.z = z1.x + acc.z * inv;
    r.w = z1.y + acc.w * inv;
    r.x = (r.x > 0.f) ? r.x : expm1f(r.x);
    r.y = (r.y > 0.f) ? r.y : expm1f(r.y);
    r.z = (r.z > 0.f) ? r.z : expm1f(r.z);
    r.w = (r.w > 0.f) ? r.w : expm1f(r.w);

    if (LAST) {
        float* o = (float*)outv + (size_t)node * HIDDEN;
        *(float2*)(o + c0)     = make_float2(r.x, r.y);
        *(float2*)(o + c0 + 8) = make_float2(r.z, r.w);
    } else {
        uint32_t h0, l0, h1, l1;
        split2h(make_float2(r.x, r.y), h0, l0);   // pair q0
        split2h(make_float2(r.z, r.w), h1, l1);   // pair q1
        *(uint4*)((uint2*)outv + (size_t)node * HPAIRS + pp) =
            make_uint4(h0, l0, h1, l1);
    }
}

// ---------------- launch ----------------------------------------------------------
extern "C" void kernel_launch(void* const* d_in, const int* in_sizes, int n_in,
                              void* d_out, int out_size) {
    const float* x      = (const float*)d_in[0];
    const int*   ei     = (const int*)d_in[1];
    const float* W_in   = (const float*)d_in[2];
    const float* b_in   = (const float*)d_in[3];
    const float* W_self = (const float*)d_in[4];
    const float* b_self = (const float*)d_in[5];
    const float* W_nbr  = (const float*)d_in[6];
    float*       out    = (float*)d_out;

    uint2*   hpkA; cudaGetSymbolAddress((void**)&hpkA, g_hpkA);
    uint2*   hpkB; cudaGetSymbolAddress((void**)&hpkB, g_hpkB);
    __half2* t16;  cudaGetSymbolAddress((void**)&t16,  g_t16);
    float*   z;    cudaGetSymbolAddress((void**)&z,    g_z);
    uint4*   w4;   cudaGetSymbolAddress((void**)&w4,   g_w4);

    const int M = N_NODES;

    initconv_k<<<NBLK, 256>>>(ei, W_in, W_nbr, W_self);
    gemm_in_count_k<<<GEMM_BLOCKS + NBLK, 256>>>(x, w4, b_in, hpkA, ei, M);
    scanfill_k<<<NBLK + FILL_BLOCKS, 256>>>(ei);

    const uint2* hcur = hpkA;
    for (int l = 0; l < NUM_LAYERS; l++) {
        const float* bs = b_self + (size_t)l * HIDDEN;
        const uint4* wn = w4 + 1024 + l * 2048;
        const uint4* ws = w4 + 1024 + (3 + l) * 2048;
        uint2* hnext = (hcur == hpkA) ? hpkB : hpkA;

        dim3 grid(GEMM_BLOCKS, 2);
        gemm_layer_k<<<grid, 256>>>(hcur, wn, ws, bs, t16, z, M);
        if (l == NUM_LAYERS - 1)
            gather_fused_k<1><<<(N_NODES * 32 + 255) / 256, 256>>>(t16, z, out);
        else
            gather_fused_k<0><<<(N_NODES * 32 + 255) / 256, 256>>>(t16, z, hnext);

        hcur = hnext;
    }
}